// round 1
// baseline (speedup 1.0000x reference)
#include <cuda_runtime.h>

#define NHEADS 12
#define SEQ 197
#define CDIM 768
#define HD 64
#define QKV3 2304
#define BATCH 128
#define MROWS (BATCH * SEQ)   // 25216

// Scratch (device globals: allocation-guard safe)
__device__ float g_qkv[(size_t)BATCH * SEQ * QKV3];   // 232 MB
__device__ float g_attn[(size_t)BATCH * SEQ * CDIM];  // 77 MB
__device__ float g_bias[QKV3];

// ---------------------------------------------------------------------------
// Composite qkv bias: [q_bias, zeros, v_bias]
// ---------------------------------------------------------------------------
__global__ void build_bias_kernel(const float* __restrict__ qb,
                                  const float* __restrict__ vb) {
    int i = blockIdx.x * blockDim.x + threadIdx.x;
    if (i < QKV3) {
        g_bias[i] = (i < CDIM) ? qb[i] : ((i < 2 * CDIM) ? 0.0f : vb[i - 2 * CDIM]);
    }
}

// ---------------------------------------------------------------------------
// SGEMM: C[m,n] = sum_k A[m,k] * B[n,k] + bias[n]
// A: [M,K] row-major, B: [N,K] row-major (i.e. x @ W^T). M%128==0, N%128==0, K%16==0.
// 128x128x16 tile, 256 threads, 8x8 register tile.
// ---------------------------------------------------------------------------
__global__ __launch_bounds__(256, 2)
void sgemm_tn_bias(const float* __restrict__ A, const float* __restrict__ Bm,
                   const float* __restrict__ bias, float* __restrict__ C,
                   int M, int N, int K) {
    __shared__ float As[16][128];
    __shared__ float Bs[16][128];

    int tid = threadIdx.x;
    int tx = tid & 15;        // 0..15  (col group)
    int ty = tid >> 4;        // 0..15  (row group)
    int m0 = blockIdx.y << 7;
    int n0 = blockIdx.x << 7;

    const float* Ab = A + (size_t)m0 * K;
    const float* Bb = Bm + (size_t)n0 * K;

    float acc[8][8];
#pragma unroll
    for (int i = 0; i < 8; i++)
#pragma unroll
        for (int j = 0; j < 8; j++) acc[i][j] = 0.0f;

    for (int k0 = 0; k0 < K; k0 += 16) {
#pragma unroll
        for (int it = 0; it < 2; it++) {
            int l = tid + it * 256;       // 0..511
            int r = l >> 2;               // row in tile 0..127
            int c = (l & 3) << 2;         // k offset 0,4,8,12
            float4 av = *(const float4*)(Ab + (size_t)r * K + k0 + c);
            As[c + 0][r] = av.x; As[c + 1][r] = av.y;
            As[c + 2][r] = av.z; As[c + 3][r] = av.w;
            float4 bv = *(const float4*)(Bb + (size_t)r * K + k0 + c);
            Bs[c + 0][r] = bv.x; Bs[c + 1][r] = bv.y;
            Bs[c + 2][r] = bv.z; Bs[c + 3][r] = bv.w;
        }
        __syncthreads();
#pragma unroll
        for (int kk = 0; kk < 16; kk++) {
            float a[8], b[8];
            *(float4*)(a)     = *(const float4*)&As[kk][ty * 8];
            *(float4*)(a + 4) = *(const float4*)&As[kk][ty * 8 + 4];
            *(float4*)(b)     = *(const float4*)&Bs[kk][tx * 8];
            *(float4*)(b + 4) = *(const float4*)&Bs[kk][tx * 8 + 4];
#pragma unroll
            for (int i = 0; i < 8; i++)
#pragma unroll
                for (int j = 0; j < 8; j++) acc[i][j] += a[i] * b[j];
        }
        __syncthreads();
    }

#pragma unroll
    for (int i = 0; i < 8; i++) {
        int m = m0 + ty * 8 + i;
        float* Crow = C + (size_t)m * N + n0 + tx * 8;
        const float* brow = bias + n0 + tx * 8;
#pragma unroll
        for (int j4 = 0; j4 < 8; j4 += 4) {
            float4 o;
            o.x = acc[i][j4 + 0] + brow[j4 + 0];
            o.y = acc[i][j4 + 1] + brow[j4 + 1];
            o.z = acc[i][j4 + 2] + brow[j4 + 2];
            o.w = acc[i][j4 + 3] + brow[j4 + 3];
            *(float4*)(Crow + j4) = o;
        }
    }
}

// ---------------------------------------------------------------------------
// Attention: one block per (b, h). K,V tiles resident in smem, 4 query rows
// per iteration (4x reuse of K/V smem loads), warp-per-row softmax.
// ---------------------------------------------------------------------------
#define KV_PAD 65
#define ATTN_SMEM_FLOATS (SEQ * KV_PAD * 2 + 256 + 800 + 1024 + 4)

__global__ __launch_bounds__(256)
void attn_kernel(const float* __restrict__ table, const int* __restrict__ relidx) {
    extern __shared__ float sm[];
    float* Ks   = sm;                     // SEQ*65
    float* Vs   = Ks + SEQ * KV_PAD;      // SEQ*65
    float* qs   = Vs + SEQ * KV_PAD;      // 4*64
    float* ps   = qs + 256;               // 4*200
    float* red  = ps + 800;               // 4 rows * 4 groups * 64
    float* invs = red + 1024;             // 4

    int tid = threadIdx.x;
    int h = blockIdx.x;
    int b = blockIdx.y;
    const float* qkv = g_qkv + (size_t)b * SEQ * QKV3;
    int hoff = h * HD;

    // Load K and V for this (b,h) into smem
    for (int idx = tid; idx < SEQ * HD; idx += 256) {
        int j = idx >> 6, d = idx & 63;
        Ks[j * KV_PAD + d] = qkv[j * QKV3 + CDIM + hoff + d];
        Vs[j * KV_PAD + d] = qkv[j * QKV3 + 2 * CDIM + hoff + d];
    }
    __syncthreads();

    const float scale = 0.125f;  // 64^-0.5
    int lane = tid & 31, wid = tid >> 5;

    for (int i0 = 0; i0 < SEQ; i0 += 4) {
        // Load 4 scaled q rows
        {
            int r = tid >> 6, d = tid & 63;
            int i = i0 + r;
            qs[tid] = (i < SEQ) ? qkv[i * QKV3 + hoff + d] * scale : 0.0f;
        }
        __syncthreads();

        // Scores: thread j computes s[r] for 4 rows
        if (tid < SEQ) {
            int j = tid;
            const float* krow = Ks + j * KV_PAD;
            float s0 = 0.f, s1 = 0.f, s2 = 0.f, s3 = 0.f;
#pragma unroll 8
            for (int d = 0; d < HD; d++) {
                float kv = krow[d];
                s0 += qs[d] * kv;
                s1 += qs[64 + d] * kv;
                s2 += qs[128 + d] * kv;
                s3 += qs[192 + d] * kv;
            }
            float sv[4] = {s0, s1, s2, s3};
#pragma unroll
            for (int r = 0; r < 4; r++) {
                int i = i0 + r;
                if (i < SEQ) {
                    ps[r * 200 + j] = sv[r] + table[relidx[i * SEQ + j] * NHEADS + h];
                }
            }
        }
        __syncthreads();

        // Softmax: warp r handles row i0+r
        if (wid < 4 && (i0 + wid) < SEQ) {
            float* pr = ps + wid * 200;
            float mx = -1e30f;
            for (int j = lane; j < SEQ; j += 32) mx = fmaxf(mx, pr[j]);
#pragma unroll
            for (int o = 16; o; o >>= 1) mx = fmaxf(mx, __shfl_xor_sync(0xffffffffu, mx, o));
            float sum = 0.f;
            for (int j = lane; j < SEQ; j += 32) {
                float e = __expf(pr[j] - mx);
                pr[j] = e;
                sum += e;
            }
#pragma unroll
            for (int o = 16; o; o >>= 1) sum += __shfl_xor_sync(0xffffffffu, sum, o);
            if (lane == 0) invs[wid] = 1.0f / sum;
        }
        __syncthreads();

        // PV: thread (d = tid&63, g = tid>>6) accumulates partial over j = g::4
        {
            int d = tid & 63, g = tid >> 6;
            float a0 = 0.f, a1 = 0.f, a2 = 0.f, a3 = 0.f;
#pragma unroll 4
            for (int j = g; j < SEQ; j += 4) {
                float v = Vs[j * KV_PAD + d];
                a0 += ps[j] * v;
                a1 += ps[200 + j] * v;
                a2 += ps[400 + j] * v;
                a3 += ps[600 + j] * v;
            }
            red[(0 * 4 + g) * 64 + d] = a0;
            red[(1 * 4 + g) * 64 + d] = a1;
            red[(2 * 4 + g) * 64 + d] = a2;
            red[(3 * 4 + g) * 64 + d] = a3;
        }
        __syncthreads();

        // Reduce partials and write out
        {
            int d = tid & 63, r = tid >> 6;
            int i = i0 + r;
            if (i < SEQ) {
                const float* rr = red + r * 4 * 64 + d;
                float s = rr[0] + rr[64] + rr[128] + rr[192];
                g_attn[((size_t)b * SEQ + i) * CDIM + hoff + d] = s * invs[r];
            }
        }
        __syncthreads();
    }
}

// ---------------------------------------------------------------------------
// Launch
// ---------------------------------------------------------------------------
extern "C" void kernel_launch(void* const* d_in, const int* in_sizes, int n_in,
                              void* d_out, int out_size) {
    const float* x      = (const float*)d_in[0];
    const float* qkv_w  = (const float*)d_in[1];
    const float* q_bias = (const float*)d_in[2];
    const float* v_bias = (const float*)d_in[3];
    const float* table  = (const float*)d_in[4];
    const float* proj_w = (const float*)d_in[5];
    const float* proj_b = (const float*)d_in[6];
    const int*   relidx = (const int*)d_in[7];
    float* out = (float*)d_out;

    float *qkv_p, *attn_p, *bias_p;
    cudaGetSymbolAddress((void**)&qkv_p, g_qkv);
    cudaGetSymbolAddress((void**)&attn_p, g_attn);
    cudaGetSymbolAddress((void**)&bias_p, g_bias);

    const size_t attn_smem = (size_t)ATTN_SMEM_FLOATS * sizeof(float);
    cudaFuncSetAttribute(attn_kernel, cudaFuncAttributeMaxDynamicSharedMemorySize,
                         (int)attn_smem);

    // 1) composite bias
    build_bias_kernel<<<(QKV3 + 255) / 256, 256>>>(q_bias, v_bias);

    // 2) qkv = x @ qkv_w^T + bias : [25216, 2304]
    sgemm_tn_bias<<<dim3(QKV3 / 128, MROWS / 128), 256>>>(
        x, qkv_w, bias_p, qkv_p, MROWS, QKV3, CDIM);

    // 3) attention per (b, h)
    attn_kernel<<<dim3(NHEADS, BATCH), 256, attn_smem>>>(table, relidx);

    // 4) out = attn @ proj_w^T + proj_b : [25216, 768]
    sgemm_tn_bias<<<dim3(CDIM / 128, MROWS / 128), 256>>>(
        attn_p, proj_w, proj_b, out, MROWS, CDIM, CDIM);
}

// round 2
// speedup vs baseline: 2.7793x; 2.7793x over previous
#include <cuda_runtime.h>

#define NHEADS 12
#define SEQ 197
#define CDIM 768
#define HD 64
#define QKV3 2304
#define BATCH 128
#define MROWS (BATCH * SEQ)   // 25216

// Scratch (device globals: allocation-guard safe)
__device__ float g_qkv[(size_t)BATCH * SEQ * QKV3];   // 232 MB
__device__ float g_attn[(size_t)BATCH * SEQ * CDIM];  // 77 MB
__device__ float g_bias[QKV3];

// ---------------------------------------------------------------------------
// Composite qkv bias: [q_bias, zeros, v_bias]
// ---------------------------------------------------------------------------
__global__ void build_bias_kernel(const float* __restrict__ qb,
                                  const float* __restrict__ vb) {
    int i = blockIdx.x * blockDim.x + threadIdx.x;
    if (i < QKV3) {
        g_bias[i] = (i < CDIM) ? qb[i] : ((i < 2 * CDIM) ? 0.0f : vb[i - 2 * CDIM]);
    }
}

__device__ __forceinline__ float f2tf32(float x) {
    unsigned u;
    asm("cvt.rna.tf32.f32 %0, %1;" : "=r"(u) : "f"(x));
    return __uint_as_float(u);
}

// ---------------------------------------------------------------------------
// TF32 tensor-core SGEMM: C[m,n] = sum_k A[m,k]*B[n,k] + bias[n]
// Block tile 128x128x32, 256 threads (8 warps 4x2), warp tile 32x64,
// mma.sync.m16n8k8.tf32. M%128==0, N%128==0, K%32==0.
// ---------------------------------------------------------------------------
#define KPAD 36

__global__ __launch_bounds__(256, 2)
void gemm_tf32_bias(const float* __restrict__ A, const float* __restrict__ Bm,
                    const float* __restrict__ bias, float* __restrict__ C,
                    int M, int N, int K) {
    __shared__ float As[128 * KPAD];
    __shared__ float Bs[128 * KPAD];

    const int tid = threadIdx.x;
    const int lane = tid & 31;
    const int warp = tid >> 5;
    const int wm = warp >> 1;          // 0..3
    const int wn = warp & 1;           // 0..1
    const int g = lane >> 2;           // 0..7
    const int tig = lane & 3;          // 0..3

    const int m0 = blockIdx.y << 7;
    const int n0 = blockIdx.x << 7;

    const float* Ab = A + (size_t)m0 * K;
    const float* Bb = Bm + (size_t)n0 * K;

    float acc[2][8][4];
#pragma unroll
    for (int mt = 0; mt < 2; mt++)
#pragma unroll
        for (int nt = 0; nt < 8; nt++)
#pragma unroll
            for (int c = 0; c < 4; c++) acc[mt][nt][c] = 0.0f;

    const int lr = tid >> 3;           // 0..31 row step base (per iter +32)
    const int lc = (tid & 7) << 2;     // 0,4,..,28

    for (int k0 = 0; k0 < K; k0 += 32) {
        // ---- fill smem (convert to tf32 once) ----
#pragma unroll
        for (int it = 0; it < 4; it++) {
            int r = lr + it * 32;      // 0..127
            float4 av = *(const float4*)(Ab + (size_t)r * K + k0 + lc);
            float4 bv = *(const float4*)(Bb + (size_t)r * K + k0 + lc);
            float4 ac = make_float4(f2tf32(av.x), f2tf32(av.y), f2tf32(av.z), f2tf32(av.w));
            float4 bc = make_float4(f2tf32(bv.x), f2tf32(bv.y), f2tf32(bv.z), f2tf32(bv.w));
            *(float4*)&As[r * KPAD + lc] = ac;
            *(float4*)&Bs[r * KPAD + lc] = bc;
        }
        __syncthreads();

        // ---- 4 k-steps of m16n8k8 ----
#pragma unroll
        for (int kk = 0; kk < 4; kk++) {
            const int kb = kk * 8;
            unsigned a[2][4];
#pragma unroll
            for (int mt = 0; mt < 2; mt++) {
                const float* ar0 = &As[(wm * 32 + mt * 16 + g) * KPAD + kb];
                const float* ar1 = &As[(wm * 32 + mt * 16 + g + 8) * KPAD + kb];
                a[mt][0] = __float_as_uint(ar0[tig]);
                a[mt][1] = __float_as_uint(ar1[tig]);
                a[mt][2] = __float_as_uint(ar0[tig + 4]);
                a[mt][3] = __float_as_uint(ar1[tig + 4]);
            }
            unsigned bfr[8][2];
#pragma unroll
            for (int nt = 0; nt < 8; nt++) {
                const float* br = &Bs[(wn * 64 + nt * 8 + g) * KPAD + kb];
                bfr[nt][0] = __float_as_uint(br[tig]);
                bfr[nt][1] = __float_as_uint(br[tig + 4]);
            }
#pragma unroll
            for (int nt = 0; nt < 8; nt++) {
#pragma unroll
                for (int mt = 0; mt < 2; mt++) {
                    asm volatile(
                        "mma.sync.aligned.m16n8k8.row.col.f32.tf32.tf32.f32 "
                        "{%0,%1,%2,%3}, {%4,%5,%6,%7}, {%8,%9}, {%0,%1,%2,%3};"
                        : "+f"(acc[mt][nt][0]), "+f"(acc[mt][nt][1]),
                          "+f"(acc[mt][nt][2]), "+f"(acc[mt][nt][3])
                        : "r"(a[mt][0]), "r"(a[mt][1]), "r"(a[mt][2]), "r"(a[mt][3]),
                          "r"(bfr[nt][0]), "r"(bfr[nt][1]));
                }
            }
        }
        __syncthreads();
    }

    // ---- epilogue: C rows (m0 + wm*32 + mt*16 + g/+8), cols (n0 + wn*64 + nt*8 + tig*2) ----
#pragma unroll
    for (int mt = 0; mt < 2; mt++) {
#pragma unroll
        for (int nt = 0; nt < 8; nt++) {
            int col = n0 + wn * 64 + nt * 8 + tig * 2;
            float b0 = bias[col], b1 = bias[col + 1];
            int row0 = m0 + wm * 32 + mt * 16 + g;
            float2 o0 = make_float2(acc[mt][nt][0] + b0, acc[mt][nt][1] + b1);
            float2 o1 = make_float2(acc[mt][nt][2] + b0, acc[mt][nt][3] + b1);
            *(float2*)(C + (size_t)row0 * N + col) = o0;
            *(float2*)(C + (size_t)(row0 + 8) * N + col) = o1;
        }
    }
}

// ---------------------------------------------------------------------------
// Attention: one block per (b, h). K,V resident in smem, 4 q-rows per iter.
// ---------------------------------------------------------------------------
#define KV_PAD 65
#define ATTN_SMEM_FLOATS (SEQ * KV_PAD * 2 + 256 + 800 + 1024 + 4)

__global__ __launch_bounds__(256)
void attn_kernel(const float* __restrict__ table, const int* __restrict__ relidx) {
    extern __shared__ float sm[];
    float* Ks   = sm;                     // SEQ*65
    float* Vs   = Ks + SEQ * KV_PAD;      // SEQ*65
    float* qs   = Vs + SEQ * KV_PAD;      // 4*64
    float* ps   = qs + 256;               // 4*200
    float* red  = ps + 800;               // 4 rows * 4 groups * 64
    float* invs = red + 1024;             // 4

    int tid = threadIdx.x;
    int h = blockIdx.x;
    int b = blockIdx.y;
    const float* qkv = g_qkv + (size_t)b * SEQ * QKV3;
    int hoff = h * HD;

    for (int idx = tid; idx < SEQ * HD; idx += 256) {
        int j = idx >> 6, d = idx & 63;
        Ks[j * KV_PAD + d] = qkv[j * QKV3 + CDIM + hoff + d];
        Vs[j * KV_PAD + d] = qkv[j * QKV3 + 2 * CDIM + hoff + d];
    }
    __syncthreads();

    const float scale = 0.125f;
    int lane = tid & 31, wid = tid >> 5;

    for (int i0 = 0; i0 < SEQ; i0 += 4) {
        {
            int r = tid >> 6, d = tid & 63;
            int i = i0 + r;
            qs[tid] = (i < SEQ) ? qkv[i * QKV3 + hoff + d] * scale : 0.0f;
        }
        __syncthreads();

        if (tid < SEQ) {
            int j = tid;
            const float* krow = Ks + j * KV_PAD;
            float s0 = 0.f, s1 = 0.f, s2 = 0.f, s3 = 0.f;
#pragma unroll 8
            for (int d = 0; d < HD; d++) {
                float kv = krow[d];
                s0 += qs[d] * kv;
                s1 += qs[64 + d] * kv;
                s2 += qs[128 + d] * kv;
                s3 += qs[192 + d] * kv;
            }
            float sv[4] = {s0, s1, s2, s3};
#pragma unroll
            for (int r = 0; r < 4; r++) {
                int i = i0 + r;
                if (i < SEQ) {
                    ps[r * 200 + j] = sv[r] + table[relidx[i * SEQ + j] * NHEADS + h];
                }
            }
        }
        __syncthreads();

        if (wid < 4 && (i0 + wid) < SEQ) {
            float* pr = ps + wid * 200;
            float mx = -1e30f;
            for (int j = lane; j < SEQ; j += 32) mx = fmaxf(mx, pr[j]);
#pragma unroll
            for (int o = 16; o; o >>= 1) mx = fmaxf(mx, __shfl_xor_sync(0xffffffffu, mx, o));
            float sum = 0.f;
            for (int j = lane; j < SEQ; j += 32) {
                float e = __expf(pr[j] - mx);
                pr[j] = e;
                sum += e;
            }
#pragma unroll
            for (int o = 16; o; o >>= 1) sum += __shfl_xor_sync(0xffffffffu, sum, o);
            if (lane == 0) invs[wid] = 1.0f / sum;
        }
        __syncthreads();

        {
            int d = tid & 63, g = tid >> 6;
            float a0 = 0.f, a1 = 0.f, a2 = 0.f, a3 = 0.f;
#pragma unroll 4
            for (int j = g; j < SEQ; j += 4) {
                float v = Vs[j * KV_PAD + d];
                a0 += ps[j] * v;
                a1 += ps[200 + j] * v;
                a2 += ps[400 + j] * v;
                a3 += ps[600 + j] * v;
            }
            red[(0 * 4 + g) * 64 + d] = a0;
            red[(1 * 4 + g) * 64 + d] = a1;
            red[(2 * 4 + g) * 64 + d] = a2;
            red[(3 * 4 + g) * 64 + d] = a3;
        }
        __syncthreads();

        {
            int d = tid & 63, r = tid >> 6;
            int i = i0 + r;
            if (i < SEQ) {
                const float* rr = red + r * 4 * 64 + d;
                float s = rr[0] + rr[64] + rr[128] + rr[192];
                g_attn[((size_t)b * SEQ + i) * CDIM + hoff + d] = s * invs[r];
            }
        }
        __syncthreads();
    }
}

// ---------------------------------------------------------------------------
// Launch
// ---------------------------------------------------------------------------
extern "C" void kernel_launch(void* const* d_in, const int* in_sizes, int n_in,
                              void* d_out, int out_size) {
    const float* x      = (const float*)d_in[0];
    const float* qkv_w  = (const float*)d_in[1];
    const float* q_bias = (const float*)d_in[2];
    const float* v_bias = (const float*)d_in[3];
    const float* table  = (const float*)d_in[4];
    const float* proj_w = (const float*)d_in[5];
    const float* proj_b = (const float*)d_in[6];
    const int*   relidx = (const int*)d_in[7];
    float* out = (float*)d_out;

    float *qkv_p, *attn_p, *bias_p;
    cudaGetSymbolAddress((void**)&qkv_p, g_qkv);
    cudaGetSymbolAddress((void**)&attn_p, g_attn);
    cudaGetSymbolAddress((void**)&bias_p, g_bias);

    const size_t attn_smem = (size_t)ATTN_SMEM_FLOATS * sizeof(float);
    cudaFuncSetAttribute(attn_kernel, cudaFuncAttributeMaxDynamicSharedMemorySize,
                         (int)attn_smem);

    build_bias_kernel<<<(QKV3 + 255) / 256, 256>>>(q_bias, v_bias);

    // qkv = x @ qkv_w^T + bias : [25216, 2304]
    gemm_tf32_bias<<<dim3(QKV3 / 128, MROWS / 128), 256>>>(
        x, qkv_w, bias_p, qkv_p, MROWS, QKV3, CDIM);

    attn_kernel<<<dim3(NHEADS, BATCH), 256, attn_smem>>>(table, relidx);

    // out = attn @ proj_w^T + proj_b : [25216, 768]
    gemm_tf32_bias<<<dim3(CDIM / 128, MROWS / 128), 256>>>(
        attn_p, proj_w, proj_b, out, MROWS, CDIM, CDIM);
}

// round 4
// speedup vs baseline: 4.9710x; 1.7886x over previous
#include <cuda_runtime.h>

#define NHEADS 12
#define SEQ 197
#define CDIM 768
#define HD 64
#define QKV3 2304
#define BATCH 128
#define MROWS (BATCH * SEQ)   // 25216
#define SPAD 224              // padded col count for relbias
#define BH (BATCH * NHEADS)   // 1536

// Scratch (device globals: allocation-guard safe)
__device__ float g_qkv[(size_t)BATCH * SEQ * QKV3];        // 232 MB
__device__ float g_attn[(size_t)BATCH * SEQ * CDIM];       // 77 MB
__device__ float g_relbias[(size_t)NHEADS * SEQ * SPAD];   // 2.1 MB
__device__ float g_bias[QKV3];

// ---------------------------------------------------------------------------
__global__ void build_bias_kernel(const float* __restrict__ qb,
                                  const float* __restrict__ vb) {
    int i = blockIdx.x * blockDim.x + threadIdx.x;
    if (i < QKV3) {
        g_bias[i] = (i < CDIM) ? qb[i] : ((i < 2 * CDIM) ? 0.0f : vb[i - 2 * CDIM]);
    }
}

__global__ void build_relbias_kernel(const float* __restrict__ table,
                                     const int* __restrict__ relidx) {
    int idx = blockIdx.x * blockDim.x + threadIdx.x;
    if (idx >= NHEADS * SEQ * SPAD) return;
    int h = idx / (SEQ * SPAD);
    int rem = idx - h * SEQ * SPAD;
    int i = rem / SPAD;
    int j = rem - i * SPAD;
    g_relbias[idx] = (j < SEQ) ? table[relidx[i * SEQ + j] * NHEADS + h] : 0.0f;
}

__device__ __forceinline__ float f2tf32(float x) {
    unsigned u;
    asm("cvt.rna.tf32.f32 %0, %1;" : "=r"(u) : "f"(x));
    return __uint_as_float(u);
}

#define KPAD 36

// ---------------------------------------------------------------------------
// TF32 GEMM: C[m,n] = sum_k A[m,k]*B[n,k] + bias[n]; 128x128x32 tiles.
// (unchanged from R2 — known good)
// ---------------------------------------------------------------------------
__global__ __launch_bounds__(256, 2)
void gemm_tf32_bias(const float* __restrict__ A, const float* __restrict__ Bm,
                    const float* __restrict__ bias, float* __restrict__ C,
                    int M, int N, int K) {
    __shared__ float As[128 * KPAD];
    __shared__ float Bs[128 * KPAD];

    const int tid = threadIdx.x;
    const int lane = tid & 31;
    const int warp = tid >> 5;
    const int wm = warp >> 1, wn = warp & 1;
    const int g = lane >> 2, tig = lane & 3;
    const int m0 = blockIdx.y << 7, n0 = blockIdx.x << 7;
    const float* Ab = A + (size_t)m0 * K;
    const float* Bb = Bm + (size_t)n0 * K;

    float acc[2][8][4];
#pragma unroll
    for (int mt = 0; mt < 2; mt++)
#pragma unroll
        for (int nt = 0; nt < 8; nt++)
#pragma unroll
            for (int c = 0; c < 4; c++) acc[mt][nt][c] = 0.0f;

    const int lr = tid >> 3;
    const int lc = (tid & 7) << 2;

    for (int k0 = 0; k0 < K; k0 += 32) {
#pragma unroll
        for (int it = 0; it < 4; it++) {
            int r = lr + it * 32;
            float4 av = *(const float4*)(Ab + (size_t)r * K + k0 + lc);
            float4 bv = *(const float4*)(Bb + (size_t)r * K + k0 + lc);
            *(float4*)&As[r * KPAD + lc] =
                make_float4(f2tf32(av.x), f2tf32(av.y), f2tf32(av.z), f2tf32(av.w));
            *(float4*)&Bs[r * KPAD + lc] =
                make_float4(f2tf32(bv.x), f2tf32(bv.y), f2tf32(bv.z), f2tf32(bv.w));
        }
        __syncthreads();
#pragma unroll
        for (int kk = 0; kk < 4; kk++) {
            const int kb = kk * 8;
            unsigned a[2][4];
#pragma unroll
            for (int mt = 0; mt < 2; mt++) {
                const float* ar0 = &As[(wm * 32 + mt * 16 + g) * KPAD + kb];
                const float* ar1 = &As[(wm * 32 + mt * 16 + g + 8) * KPAD + kb];
                a[mt][0] = __float_as_uint(ar0[tig]);
                a[mt][1] = __float_as_uint(ar1[tig]);
                a[mt][2] = __float_as_uint(ar0[tig + 4]);
                a[mt][3] = __float_as_uint(ar1[tig + 4]);
            }
            unsigned bfr[8][2];
#pragma unroll
            for (int nt = 0; nt < 8; nt++) {
                const float* br = &Bs[(wn * 64 + nt * 8 + g) * KPAD + kb];
                bfr[nt][0] = __float_as_uint(br[tig]);
                bfr[nt][1] = __float_as_uint(br[tig + 4]);
            }
#pragma unroll
            for (int nt = 0; nt < 8; nt++)
#pragma unroll
                for (int mt = 0; mt < 2; mt++) {
                    asm volatile(
                        "mma.sync.aligned.m16n8k8.row.col.f32.tf32.tf32.f32 "
                        "{%0,%1,%2,%3}, {%4,%5,%6,%7}, {%8,%9}, {%0,%1,%2,%3};"
                        : "+f"(acc[mt][nt][0]), "+f"(acc[mt][nt][1]),
                          "+f"(acc[mt][nt][2]), "+f"(acc[mt][nt][3])
                        : "r"(a[mt][0]), "r"(a[mt][1]), "r"(a[mt][2]), "r"(a[mt][3]),
                          "r"(bfr[nt][0]), "r"(bfr[nt][1]));
                }
        }
        __syncthreads();
    }

#pragma unroll
    for (int mt = 0; mt < 2; mt++)
#pragma unroll
        for (int nt = 0; nt < 8; nt++) {
            int col = n0 + wn * 64 + nt * 8 + tig * 2;
            float b0 = bias[col], b1 = bias[col + 1];
            int row0 = m0 + wm * 32 + mt * 16 + g;
            *(float2*)(C + (size_t)row0 * N + col) =
                make_float2(acc[mt][nt][0] + b0, acc[mt][nt][1] + b1);
            *(float2*)(C + (size_t)(row0 + 8) * N + col) =
                make_float2(acc[mt][nt][2] + b0, acc[mt][nt][3] + b1);
        }
}

// ---------------------------------------------------------------------------
// Fused attention: CTA per (m-tile, b*h). S-tile -> smem P -> softmax -> P*V.
// ---------------------------------------------------------------------------
#define PSTRIDE 228
#define VPAD 68
#define FUSED_SMEM_FLOATS (128 * PSTRIDE + 2 * 128 * KPAD)  // 38400 -> 153.6 KB

__global__ __launch_bounds__(256, 1)
void fused_attn(void) {
    extern __shared__ float sm[];
    float* P  = sm;                      // [128][228]
    float* As = P + 128 * PSTRIDE;       // [128][36]
    float* Bs = As + 128 * KPAD;         // [128][36]
    float* Vs = As;                      // stage C alias: [32][68]

    const int tid = threadIdx.x;
    const int lane = tid & 31;
    const int warp = tid >> 5;
    const int wm = warp >> 1, wn = warp & 1;
    const int g = lane >> 2, tig = lane & 3;

    const int m0 = blockIdx.x << 7;                 // 0 or 128
    const int bh = blockIdx.y;
    const int b = bh / NHEADS, h = bh - b * NHEADS;
    const float* qkv = g_qkv + (size_t)b * SEQ * QKV3;
    const int hoff = h * HD;
    const float scale = 0.125f;

    const int lr = tid >> 3;
    const int lc = (tid & 7) << 2;

    // ===== Stage A: S = scale*Q*K^T + rel_bias -> P (pads = -1e30) =====
    const float* rb = g_relbias + (size_t)h * SEQ * SPAD;
#pragma unroll
    for (int n0 = 0; n0 < 256; n0 += 128) {
        float acc[2][8][4];
#pragma unroll
        for (int mt = 0; mt < 2; mt++)
#pragma unroll
            for (int nt = 0; nt < 8; nt++)
#pragma unroll
                for (int c = 0; c < 4; c++) acc[mt][nt][c] = 0.0f;

#pragma unroll
        for (int k0 = 0; k0 < HD; k0 += 32) {
#pragma unroll
            for (int it = 0; it < 4; it++) {
                int r = lr + it * 32;
                int qi = min(m0 + r, SEQ - 1);
                int kj = min(n0 + r, SEQ - 1);
                float4 av = *(const float4*)(qkv + (size_t)qi * QKV3 + hoff + k0 + lc);
                float4 bv = *(const float4*)(qkv + (size_t)kj * QKV3 + CDIM + hoff + k0 + lc);
                *(float4*)&As[r * KPAD + lc] =
                    make_float4(f2tf32(av.x * scale), f2tf32(av.y * scale),
                                f2tf32(av.z * scale), f2tf32(av.w * scale));
                *(float4*)&Bs[r * KPAD + lc] =
                    make_float4(f2tf32(bv.x), f2tf32(bv.y), f2tf32(bv.z), f2tf32(bv.w));
            }
            __syncthreads();
#pragma unroll
            for (int kk = 0; kk < 4; kk++) {
                const int kb = kk * 8;
                unsigned a[2][4];
#pragma unroll
                for (int mt = 0; mt < 2; mt++) {
                    const float* ar0 = &As[(wm * 32 + mt * 16 + g) * KPAD + kb];
                    const float* ar1 = &As[(wm * 32 + mt * 16 + g + 8) * KPAD + kb];
                    a[mt][0] = __float_as_uint(ar0[tig]);
                    a[mt][1] = __float_as_uint(ar1[tig]);
                    a[mt][2] = __float_as_uint(ar0[tig + 4]);
                    a[mt][3] = __float_as_uint(ar1[tig + 4]);
                }
                unsigned bfr[8][2];
#pragma unroll
                for (int nt = 0; nt < 8; nt++) {
                    const float* br = &Bs[(wn * 64 + nt * 8 + g) * KPAD + kb];
                    bfr[nt][0] = __float_as_uint(br[tig]);
                    bfr[nt][1] = __float_as_uint(br[tig + 4]);
                }
#pragma unroll
                for (int nt = 0; nt < 8; nt++)
#pragma unroll
                    for (int mt = 0; mt < 2; mt++) {
                        asm volatile(
                            "mma.sync.aligned.m16n8k8.row.col.f32.tf32.tf32.f32 "
                            "{%0,%1,%2,%3}, {%4,%5,%6,%7}, {%8,%9}, {%0,%1,%2,%3};"
                            : "+f"(acc[mt][nt][0]), "+f"(acc[mt][nt][1]),
                              "+f"(acc[mt][nt][2]), "+f"(acc[mt][nt][3])
                            : "r"(a[mt][0]), "r"(a[mt][1]), "r"(a[mt][2]), "r"(a[mt][3]),
                              "r"(bfr[nt][0]), "r"(bfr[nt][1]));
                    }
            }
            __syncthreads();
        }

        // epilogue -> smem P
#pragma unroll
        for (int mt = 0; mt < 2; mt++)
#pragma unroll
            for (int nt = 0; nt < 8; nt++) {
                int col = n0 + wn * 64 + nt * 8 + tig * 2;
                if (col >= PSTRIDE) continue;
                int rloc0 = wm * 32 + mt * 16 + g;
#pragma unroll
                for (int half = 0; half < 2; half++) {
                    int rloc = rloc0 + half * 8;
                    int grow = min(m0 + rloc, SEQ - 1);
                    float s0 = acc[mt][nt][half * 2 + 0];
                    float s1 = acc[mt][nt][half * 2 + 1];
                    P[rloc * PSTRIDE + col] =
                        (col < SEQ) ? s0 + rb[(size_t)grow * SPAD + col] : -1e30f;
                    P[rloc * PSTRIDE + col + 1] =
                        (col + 1 < SEQ) ? s1 + rb[(size_t)grow * SPAD + col + 1] : -1e30f;
                }
            }
    }
    __syncthreads();

    // ===== Stage B: softmax rows of P (warp per row, 16 rows per warp) =====
    for (int rloc = warp; rloc < 128; rloc += 8) {
        float* pr = P + rloc * PSTRIDE;
        float mx = -1e30f;
        float ev[7];
#pragma unroll
        for (int t = 0; t < 7; t++) {
            ev[t] = pr[lane + t * 32];
            mx = fmaxf(mx, ev[t]);
        }
#pragma unroll
        for (int o = 16; o; o >>= 1) mx = fmaxf(mx, __shfl_xor_sync(0xffffffffu, mx, o));
        float sum = 0.f;
#pragma unroll
        for (int t = 0; t < 7; t++) {
            ev[t] = __expf(ev[t] - mx);
            sum += ev[t];
        }
#pragma unroll
        for (int o = 16; o; o >>= 1) sum += __shfl_xor_sync(0xffffffffu, sum, o);
        float inv = 1.0f / sum;
#pragma unroll
        for (int t = 0; t < 7; t++) pr[lane + t * 32] = f2tf32(ev[t] * inv);
    }

    // ===== Stage C: O = P * V =====
    float acc[2][4][4];
#pragma unroll
    for (int mt = 0; mt < 2; mt++)
#pragma unroll
        for (int nt = 0; nt < 4; nt++)
#pragma unroll
            for (int c = 0; c < 4; c++) acc[mt][nt][c] = 0.0f;

    const int vr = tid >> 4;           // 0..15
    const int vc = (tid & 15) << 2;    // 0..60

    for (int k0 = 0; k0 < SPAD; k0 += 32) {
        __syncthreads();
#pragma unroll
        for (int it = 0; it < 2; it++) {
            int j = vr + it * 16;
            int vj = min(k0 + j, SEQ - 1);
            float4 vv = *(const float4*)(qkv + (size_t)vj * QKV3 + 2 * CDIM + hoff + vc);
            *(float4*)&Vs[j * VPAD + vc] =
                make_float4(f2tf32(vv.x), f2tf32(vv.y), f2tf32(vv.z), f2tf32(vv.w));
        }
        __syncthreads();
#pragma unroll
        for (int kk = 0; kk < 4; kk++) {
            const int kb = kk * 8;
            unsigned a[2][4];
#pragma unroll
            for (int mt = 0; mt < 2; mt++) {
                const float* ar0 = &P[(wm * 32 + mt * 16 + g) * PSTRIDE + k0 + kb];
                const float* ar1 = &P[(wm * 32 + mt * 16 + g + 8) * PSTRIDE + k0 + kb];
                a[mt][0] = __float_as_uint(ar0[tig]);
                a[mt][1] = __float_as_uint(ar1[tig]);
                a[mt][2] = __float_as_uint(ar0[tig + 4]);
                a[mt][3] = __float_as_uint(ar1[tig + 4]);
            }
            unsigned bfr[4][2];
#pragma unroll
            for (int nt = 0; nt < 4; nt++) {
                int n = wn * 32 + nt * 8 + g;
                bfr[nt][0] = __float_as_uint(Vs[(kb + tig) * VPAD + n]);
                bfr[nt][1] = __float_as_uint(Vs[(kb + tig + 4) * VPAD + n]);
            }
#pragma unroll
            for (int nt = 0; nt < 4; nt++)
#pragma unroll
                for (int mt = 0; mt < 2; mt++) {
                    asm volatile(
                        "mma.sync.aligned.m16n8k8.row.col.f32.tf32.tf32.f32 "
                        "{%0,%1,%2,%3}, {%4,%5,%6,%7}, {%8,%9}, {%0,%1,%2,%3};"
                        : "+f"(acc[mt][nt][0]), "+f"(acc[mt][nt][1]),
                          "+f"(acc[mt][nt][2]), "+f"(acc[mt][nt][3])
                        : "r"(a[mt][0]), "r"(a[mt][1]), "r"(a[mt][2]), "r"(a[mt][3]),
                          "r"(bfr[nt][0]), "r"(bfr[nt][1]));
                }
        }
    }

#pragma unroll
    for (int mt = 0; mt < 2; mt++)
#pragma unroll
        for (int nt = 0; nt < 4; nt++) {
            int col = wn * 32 + nt * 8 + tig * 2;
            int row0 = m0 + wm * 32 + mt * 16 + g;
            if (row0 < SEQ)
                *(float2*)(g_attn + ((size_t)b * SEQ + row0) * CDIM + hoff + col) =
                    make_float2(acc[mt][nt][0], acc[mt][nt][1]);
            int row1 = row0 + 8;
            if (row1 < SEQ)
                *(float2*)(g_attn + ((size_t)b * SEQ + row1) * CDIM + hoff + col) =
                    make_float2(acc[mt][nt][2], acc[mt][nt][3]);
        }
}

// ---------------------------------------------------------------------------
extern "C" void kernel_launch(void* const* d_in, const int* in_sizes, int n_in,
                              void* d_out, int out_size) {
    const float* x      = (const float*)d_in[0];
    const float* qkv_w  = (const float*)d_in[1];
    const float* q_bias = (const float*)d_in[2];
    const float* v_bias = (const float*)d_in[3];
    const float* table  = (const float*)d_in[4];
    const float* proj_w = (const float*)d_in[5];
    const float* proj_b = (const float*)d_in[6];
    const int*   relidx = (const int*)d_in[7];
    float* out = (float*)d_out;

    float *qkv_p, *attn_p, *bias_p;
    cudaGetSymbolAddress((void**)&qkv_p, g_qkv);
    cudaGetSymbolAddress((void**)&attn_p, g_attn);
    cudaGetSymbolAddress((void**)&bias_p, g_bias);

    const size_t fused_smem = (size_t)FUSED_SMEM_FLOATS * sizeof(float);
    cudaFuncSetAttribute(fused_attn, cudaFuncAttributeMaxDynamicSharedMemorySize,
                         (int)fused_smem);

    build_bias_kernel<<<(QKV3 + 255) / 256, 256>>>(q_bias, v_bias);
    build_relbias_kernel<<<(NHEADS * SEQ * SPAD + 255) / 256, 256>>>(table, relidx);

    // qkv = x @ qkv_w^T + bias
    gemm_tf32_bias<<<dim3(QKV3 / 128, MROWS / 128), 256>>>(
        x, qkv_w, bias_p, qkv_p, MROWS, QKV3, CDIM);

    // fused attention -> g_attn
    fused_attn<<<dim3(2, BH), 256, fused_smem>>>();

    // out = attn @ proj_w^T + proj_b
    gemm_tf32_bias<<<dim3(CDIM / 128, MROWS / 128), 256>>>(
        attn_p, proj_w, proj_b, out, MROWS, CDIM, CDIM);
}

// round 5
// speedup vs baseline: 5.2606x; 1.0583x over previous
#include <cuda_runtime.h>

#define NHEADS 12
#define SEQ 197
#define CDIM 768
#define HD 64
#define QKV3 2304
#define BATCH 128
#define MROWS (BATCH * SEQ)   // 25216
#define SPAD 224              // padded col count for relbias
#define BH (BATCH * NHEADS)   // 1536

// Scratch (device globals: allocation-guard safe)
__device__ float g_qkv[(size_t)BATCH * SEQ * QKV3];        // 232 MB
__device__ float g_attn[(size_t)BATCH * SEQ * CDIM];       // 77 MB
__device__ float g_relbias[(size_t)NHEADS * SEQ * SPAD];   // 2.1 MB
__device__ float g_bias[QKV3];

// ---------------------------------------------------------------------------
__global__ void build_bias_kernel(const float* __restrict__ qb,
                                  const float* __restrict__ vb) {
    int i = blockIdx.x * blockDim.x + threadIdx.x;
    if (i < QKV3) {
        g_bias[i] = (i < CDIM) ? qb[i] : ((i < 2 * CDIM) ? 0.0f : vb[i - 2 * CDIM]);
    }
}

__global__ void build_relbias_kernel(const float* __restrict__ table,
                                     const int* __restrict__ relidx) {
    int idx = blockIdx.x * blockDim.x + threadIdx.x;
    if (idx >= NHEADS * SEQ * SPAD) return;
    int h = idx / (SEQ * SPAD);
    int rem = idx - h * SEQ * SPAD;
    int i = rem / SPAD;
    int j = rem - i * SPAD;
    g_relbias[idx] = (j < SEQ) ? table[relidx[i * SEQ + j] * NHEADS + h] : 0.0f;
}

__device__ __forceinline__ float f2tf32(float x) {
    unsigned u;
    asm("cvt.rna.tf32.f32 %0, %1;" : "=r"(u) : "f"(x));
    return __uint_as_float(u);
}

// load float from smem and convert to tf32 bits
__device__ __forceinline__ unsigned ldtf(const float* p) {
    unsigned u;
    asm("cvt.rna.tf32.f32 %0, %1;" : "=r"(u) : "f"(*p));
    return u;
}

#define KPAD 36
#define TILE_F (128 * KPAD)   // 4608 floats per tile buffer

// ---------------------------------------------------------------------------
// TF32 GEMM: C[m,n] = sum_k A[m,k]*B[n,k] + bias[n]; 128x128x32 tiles.
// Double-buffered cp.async; tf32 conversion at fragment load.
// ---------------------------------------------------------------------------
__global__ __launch_bounds__(256, 2)
void gemm_tf32_bias(const float* __restrict__ A, const float* __restrict__ Bm,
                    const float* __restrict__ bias, float* __restrict__ C,
                    int M, int N, int K) {
    extern __shared__ float gsm[];
    float* Abuf = gsm;                 // [2][4608]
    float* Bbuf = gsm + 2 * TILE_F;    // [2][4608]
    unsigned sA = (unsigned)__cvta_generic_to_shared(Abuf);
    unsigned sB = (unsigned)__cvta_generic_to_shared(Bbuf);

    const int tid = threadIdx.x;
    const int lane = tid & 31;
    const int warp = tid >> 5;
    const int wm = warp >> 1, wn = warp & 1;
    const int g = lane >> 2, tig = lane & 3;
    const int m0 = blockIdx.y << 7, n0 = blockIdx.x << 7;
    const float* Ab = A + (size_t)m0 * K;
    const float* Bb = Bm + (size_t)n0 * K;

    float acc[2][8][4];
#pragma unroll
    for (int mt = 0; mt < 2; mt++)
#pragma unroll
        for (int nt = 0; nt < 8; nt++)
#pragma unroll
            for (int c = 0; c < 4; c++) acc[mt][nt][c] = 0.0f;

    const int lr = tid >> 3;           // 0..31
    const int lc = (tid & 7) << 2;     // 0,4,..,28

#define GEMM_ISSUE(K0, BUF) do {                                               \
        unsigned ao_ = sA + (unsigned)((BUF) * TILE_F) * 4u;                   \
        unsigned bo_ = sB + (unsigned)((BUF) * TILE_F) * 4u;                   \
        _Pragma("unroll")                                                      \
        for (int it_ = 0; it_ < 4; it_++) {                                    \
            int r_ = lr + it_ * 32;                                            \
            asm volatile("cp.async.cg.shared.global [%0], [%1], 16;"           \
                :: "r"(ao_ + (unsigned)(r_ * KPAD + lc) * 4u),                 \
                   "l"(Ab + (size_t)r_ * K + (K0) + lc));                      \
            asm volatile("cp.async.cg.shared.global [%0], [%1], 16;"           \
                :: "r"(bo_ + (unsigned)(r_ * KPAD + lc) * 4u),                 \
                   "l"(Bb + (size_t)r_ * K + (K0) + lc));                      \
        }                                                                      \
        asm volatile("cp.async.commit_group;");                                \
    } while (0)

    const int NT = K >> 5;
    GEMM_ISSUE(0, 0);

    for (int it = 0; it < NT; it++) {
        asm volatile("cp.async.wait_group 0;");
        __syncthreads();
        if (it + 1 < NT) GEMM_ISSUE((it + 1) << 5, (it + 1) & 1);

        const float* Ac = Abuf + (it & 1) * TILE_F;
        const float* Bc = Bbuf + (it & 1) * TILE_F;
#pragma unroll
        for (int kk = 0; kk < 4; kk++) {
            const int kb = kk * 8;
            unsigned a[2][4];
#pragma unroll
            for (int mt = 0; mt < 2; mt++) {
                const float* ar0 = &Ac[(wm * 32 + mt * 16 + g) * KPAD + kb];
                const float* ar1 = &Ac[(wm * 32 + mt * 16 + g + 8) * KPAD + kb];
                a[mt][0] = ldtf(ar0 + tig);
                a[mt][1] = ldtf(ar1 + tig);
                a[mt][2] = ldtf(ar0 + tig + 4);
                a[mt][3] = ldtf(ar1 + tig + 4);
            }
            unsigned bfr[8][2];
#pragma unroll
            for (int nt = 0; nt < 8; nt++) {
                const float* br = &Bc[(wn * 64 + nt * 8 + g) * KPAD + kb];
                bfr[nt][0] = ldtf(br + tig);
                bfr[nt][1] = ldtf(br + tig + 4);
            }
#pragma unroll
            for (int nt = 0; nt < 8; nt++)
#pragma unroll
                for (int mt = 0; mt < 2; mt++) {
                    asm volatile(
                        "mma.sync.aligned.m16n8k8.row.col.f32.tf32.tf32.f32 "
                        "{%0,%1,%2,%3}, {%4,%5,%6,%7}, {%8,%9}, {%0,%1,%2,%3};"
                        : "+f"(acc[mt][nt][0]), "+f"(acc[mt][nt][1]),
                          "+f"(acc[mt][nt][2]), "+f"(acc[mt][nt][3])
                        : "r"(a[mt][0]), "r"(a[mt][1]), "r"(a[mt][2]), "r"(a[mt][3]),
                          "r"(bfr[nt][0]), "r"(bfr[nt][1]));
                }
        }
    }

#pragma unroll
    for (int mt = 0; mt < 2; mt++)
#pragma unroll
        for (int nt = 0; nt < 8; nt++) {
            int col = n0 + wn * 64 + nt * 8 + tig * 2;
            float b0 = bias[col], b1 = bias[col + 1];
            int row0 = m0 + wm * 32 + mt * 16 + g;
            *(float2*)(C + (size_t)row0 * N + col) =
                make_float2(acc[mt][nt][0] + b0, acc[mt][nt][1] + b1);
            *(float2*)(C + (size_t)(row0 + 8) * N + col) =
                make_float2(acc[mt][nt][2] + b0, acc[mt][nt][3] + b1);
        }
}

// ---------------------------------------------------------------------------
// Fused attention, M-tile = 64 rows (2 CTAs/SM).
// Stage A: S = scale*Q*K^T + rel_bias -> smem P; Stage B: softmax; Stage C: P*V.
// ---------------------------------------------------------------------------
#define PSTRIDE 228
#define VPAD 68
#define MT 64
#define FUSED_SMEM_FLOATS (MT * PSTRIDE + MT * KPAD + 128 * KPAD)  // 21504 -> 86 KB

__global__ __launch_bounds__(256, 2)
void fused_attn(void) {
    extern __shared__ float sm[];
    float* P  = sm;                      // [64][228]
    float* As = P + MT * PSTRIDE;        // [64][36]
    float* Bs = As + MT * KPAD;          // [128][36]
    float* Vs = As;                      // stage C alias: [32][68]

    const int tid = threadIdx.x;
    const int lane = tid & 31;
    const int warp = tid >> 5;
    const int wm = warp >> 1, wn = warp & 1;   // wm 0..3 (16 rows), wn 0..1
    const int g = lane >> 2, tig = lane & 3;

    const int m0 = blockIdx.x << 6;            // 0,64,128,192
    const int bh = blockIdx.y;
    const int b = bh / NHEADS, h = bh - b * NHEADS;
    const float* qkv = g_qkv + (size_t)b * SEQ * QKV3;
    const int hoff = h * HD;
    const float scale = 0.125f;

    const int lr = tid >> 3;
    const int lc = (tid & 7) << 2;

    // ===== Stage A =====
    const float* rb = g_relbias + (size_t)h * SEQ * SPAD;
#pragma unroll
    for (int n0 = 0; n0 < 256; n0 += 128) {
        float acc[8][4];
#pragma unroll
        for (int nt = 0; nt < 8; nt++)
#pragma unroll
            for (int c = 0; c < 4; c++) acc[nt][c] = 0.0f;

#pragma unroll
        for (int k0 = 0; k0 < HD; k0 += 32) {
#pragma unroll
            for (int it = 0; it < 2; it++) {          // Q: 64 rows
                int r = lr + it * 32;
                int qi = min(m0 + r, SEQ - 1);
                float4 av = *(const float4*)(qkv + (size_t)qi * QKV3 + hoff + k0 + lc);
                *(float4*)&As[r * KPAD + lc] =
                    make_float4(f2tf32(av.x * scale), f2tf32(av.y * scale),
                                f2tf32(av.z * scale), f2tf32(av.w * scale));
            }
#pragma unroll
            for (int it = 0; it < 4; it++) {          // K: 128 rows
                int r = lr + it * 32;
                int kj = min(n0 + r, SEQ - 1);
                float4 bv = *(const float4*)(qkv + (size_t)kj * QKV3 + CDIM + hoff + k0 + lc);
                *(float4*)&Bs[r * KPAD + lc] =
                    make_float4(f2tf32(bv.x), f2tf32(bv.y), f2tf32(bv.z), f2tf32(bv.w));
            }
            __syncthreads();
#pragma unroll
            for (int kk = 0; kk < 4; kk++) {
                const int kb = kk * 8;
                unsigned a[4];
                {
                    const float* ar0 = &As[(wm * 16 + g) * KPAD + kb];
                    const float* ar1 = &As[(wm * 16 + g + 8) * KPAD + kb];
                    a[0] = __float_as_uint(ar0[tig]);
                    a[1] = __float_as_uint(ar1[tig]);
                    a[2] = __float_as_uint(ar0[tig + 4]);
                    a[3] = __float_as_uint(ar1[tig + 4]);
                }
                unsigned bfr[8][2];
#pragma unroll
                for (int nt = 0; nt < 8; nt++) {
                    const float* br = &Bs[(wn * 64 + nt * 8 + g) * KPAD + kb];
                    bfr[nt][0] = __float_as_uint(br[tig]);
                    bfr[nt][1] = __float_as_uint(br[tig + 4]);
                }
#pragma unroll
                for (int nt = 0; nt < 8; nt++) {
                    asm volatile(
                        "mma.sync.aligned.m16n8k8.row.col.f32.tf32.tf32.f32 "
                        "{%0,%1,%2,%3}, {%4,%5,%6,%7}, {%8,%9}, {%0,%1,%2,%3};"
                        : "+f"(acc[nt][0]), "+f"(acc[nt][1]),
                          "+f"(acc[nt][2]), "+f"(acc[nt][3])
                        : "r"(a[0]), "r"(a[1]), "r"(a[2]), "r"(a[3]),
                          "r"(bfr[nt][0]), "r"(bfr[nt][1]));
                }
            }
            __syncthreads();
        }

        // epilogue -> smem P (pads = -1e30)
#pragma unroll
        for (int nt = 0; nt < 8; nt++) {
            int col = n0 + wn * 64 + nt * 8 + tig * 2;
            if (col >= PSTRIDE) continue;
#pragma unroll
            for (int half = 0; half < 2; half++) {
                int rloc = wm * 16 + g + half * 8;
                int grow = min(m0 + rloc, SEQ - 1);
                float s0 = acc[nt][half * 2 + 0];
                float s1 = acc[nt][half * 2 + 1];
                P[rloc * PSTRIDE + col] =
                    (col < SEQ) ? s0 + rb[(size_t)grow * SPAD + col] : -1e30f;
                P[rloc * PSTRIDE + col + 1] =
                    (col + 1 < SEQ) ? s1 + rb[(size_t)grow * SPAD + col + 1] : -1e30f;
            }
        }
    }
    __syncthreads();

    // ===== Stage B: softmax (warp per row, 8 rows per warp) =====
    for (int rloc = warp; rloc < MT; rloc += 8) {
        float* pr = P + rloc * PSTRIDE;
        float mx = -1e30f;
        float ev[7];
#pragma unroll
        for (int t = 0; t < 7; t++) {
            ev[t] = pr[lane + t * 32];
            mx = fmaxf(mx, ev[t]);
        }
#pragma unroll
        for (int o = 16; o; o >>= 1) mx = fmaxf(mx, __shfl_xor_sync(0xffffffffu, mx, o));
        float sum = 0.f;
#pragma unroll
        for (int t = 0; t < 7; t++) {
            ev[t] = __expf(ev[t] - mx);
            sum += ev[t];
        }
#pragma unroll
        for (int o = 16; o; o >>= 1) sum += __shfl_xor_sync(0xffffffffu, sum, o);
        float inv = 1.0f / sum;
#pragma unroll
        for (int t = 0; t < 7; t++) pr[lane + t * 32] = f2tf32(ev[t] * inv);
    }

    // ===== Stage C: O = P * V =====
    float acc[4][4];
#pragma unroll
    for (int nt = 0; nt < 4; nt++)
#pragma unroll
        for (int c = 0; c < 4; c++) acc[nt][c] = 0.0f;

    const int vr = tid >> 4;           // 0..15
    const int vc = (tid & 15) << 2;    // 0..60

    for (int k0 = 0; k0 < SPAD; k0 += 32) {
        __syncthreads();
#pragma unroll
        for (int it = 0; it < 2; it++) {
            int j = vr + it * 16;
            int vj = min(k0 + j, SEQ - 1);
            float4 vv = *(const float4*)(qkv + (size_t)vj * QKV3 + 2 * CDIM + hoff + vc);
            *(float4*)&Vs[j * VPAD + vc] =
                make_float4(f2tf32(vv.x), f2tf32(vv.y), f2tf32(vv.z), f2tf32(vv.w));
        }
        __syncthreads();
#pragma unroll
        for (int kk = 0; kk < 4; kk++) {
            const int kb = kk * 8;
            unsigned a[4];
            {
                const float* ar0 = &P[(wm * 16 + g) * PSTRIDE + k0 + kb];
                const float* ar1 = &P[(wm * 16 + g + 8) * PSTRIDE + k0 + kb];
                a[0] = __float_as_uint(ar0[tig]);
                a[1] = __float_as_uint(ar1[tig]);
                a[2] = __float_as_uint(ar0[tig + 4]);
                a[3] = __float_as_uint(ar1[tig + 4]);
            }
            unsigned bfr[4][2];
#pragma unroll
            for (int nt = 0; nt < 4; nt++) {
                int n = wn * 32 + nt * 8 + g;
                bfr[nt][0] = __float_as_uint(Vs[(kb + tig) * VPAD + n]);
                bfr[nt][1] = __float_as_uint(Vs[(kb + tig + 4) * VPAD + n]);
            }
#pragma unroll
            for (int nt = 0; nt < 4; nt++) {
                asm volatile(
                    "mma.sync.aligned.m16n8k8.row.col.f32.tf32.tf32.f32 "
                    "{%0,%1,%2,%3}, {%4,%5,%6,%7}, {%8,%9}, {%0,%1,%2,%3};"
                    : "+f"(acc[nt][0]), "+f"(acc[nt][1]),
                      "+f"(acc[nt][2]), "+f"(acc[nt][3])
                    : "r"(a[0]), "r"(a[1]), "r"(a[2]), "r"(a[3]),
                      "r"(bfr[nt][0]), "r"(bfr[nt][1]));
            }
        }
    }

#pragma unroll
    for (int nt = 0; nt < 4; nt++) {
        int col = wn * 32 + nt * 8 + tig * 2;
        int row0 = m0 + wm * 16 + g;
        if (row0 < SEQ)
            *(float2*)(g_attn + ((size_t)b * SEQ + row0) * CDIM + hoff + col) =
                make_float2(acc[nt][0], acc[nt][1]);
        int row1 = row0 + 8;
        if (row1 < SEQ)
            *(float2*)(g_attn + ((size_t)b * SEQ + row1) * CDIM + hoff + col) =
                make_float2(acc[nt][2], acc[nt][3]);
    }
}

// ---------------------------------------------------------------------------
extern "C" void kernel_launch(void* const* d_in, const int* in_sizes, int n_in,
                              void* d_out, int out_size) {
    const float* x      = (const float*)d_in[0];
    const float* qkv_w  = (const float*)d_in[1];
    const float* q_bias = (const float*)d_in[2];
    const float* v_bias = (const float*)d_in[3];
    const float* table  = (const float*)d_in[4];
    const float* proj_w = (const float*)d_in[5];
    const float* proj_b = (const float*)d_in[6];
    const int*   relidx = (const int*)d_in[7];
    float* out = (float*)d_out;

    float *qkv_p, *attn_p, *bias_p;
    cudaGetSymbolAddress((void**)&qkv_p, g_qkv);
    cudaGetSymbolAddress((void**)&attn_p, g_attn);
    cudaGetSymbolAddress((void**)&bias_p, g_bias);

    const size_t gemm_smem = (size_t)4 * TILE_F * sizeof(float);       // 73728
    const size_t fused_smem = (size_t)FUSED_SMEM_FLOATS * sizeof(float); // 86016
    cudaFuncSetAttribute(gemm_tf32_bias, cudaFuncAttributeMaxDynamicSharedMemorySize,
                         (int)gemm_smem);
    cudaFuncSetAttribute(fused_attn, cudaFuncAttributeMaxDynamicSharedMemorySize,
                         (int)fused_smem);

    build_bias_kernel<<<(QKV3 + 255) / 256, 256>>>(q_bias, v_bias);
    build_relbias_kernel<<<(NHEADS * SEQ * SPAD + 255) / 256, 256>>>(table, relidx);

    // qkv = x @ qkv_w^T + bias
    gemm_tf32_bias<<<dim3(QKV3 / 128, MROWS / 128), 256, gemm_smem>>>(
        x, qkv_w, bias_p, qkv_p, MROWS, QKV3, CDIM);

    // fused attention -> g_attn
    fused_attn<<<dim3(4, BH), 256, fused_smem>>>();

    // out = attn @ proj_w^T + proj_b
    gemm_tf32_bias<<<dim3(CDIM / 128, MROWS / 128), 256, gemm_smem>>>(
        attn_p, proj_w, proj_b, out, MROWS, CDIM, CDIM);
}

// round 8
// speedup vs baseline: 5.5194x; 1.0492x over previous
#include <cuda_runtime.h>

#define NHEADS 12
#define SEQ 197
#define CDIM 768
#define HD 64
#define QKV3 2304
#define BATCH 128
#define MROWS (BATCH * SEQ)   // 25216
#define SPAD 224              // padded col count for relbias
#define BH (BATCH * NHEADS)   // 1536

// Scratch (device globals: allocation-guard safe)
__device__ float g_qkv[(size_t)BATCH * SEQ * QKV3];        // 232 MB
__device__ float g_attn[(size_t)BATCH * SEQ * CDIM];       // 77 MB
__device__ float g_relbias[(size_t)NHEADS * SEQ * SPAD];   // 2.1 MB
__device__ float g_bias[QKV3];

// ---------------------------------------------------------------------------
__global__ void build_bias_kernel(const float* __restrict__ qb,
                                  const float* __restrict__ vb) {
    int i = blockIdx.x * blockDim.x + threadIdx.x;
    if (i < QKV3) {
        g_bias[i] = (i < CDIM) ? qb[i] : ((i < 2 * CDIM) ? 0.0f : vb[i - 2 * CDIM]);
    }
}

__global__ void build_relbias_kernel(const float* __restrict__ table,
                                     const int* __restrict__ relidx) {
    int idx = blockIdx.x * blockDim.x + threadIdx.x;
    if (idx >= NHEADS * SEQ * SPAD) return;
    int h = idx / (SEQ * SPAD);
    int rem = idx - h * SEQ * SPAD;
    int i = rem / SPAD;
    int j = rem - i * SPAD;
    g_relbias[idx] = (j < SEQ) ? table[relidx[i * SEQ + j] * NHEADS + h] : 0.0f;
}

__device__ __forceinline__ float f2tf32(float x) {
    unsigned u;
    asm("cvt.rna.tf32.f32 %0, %1;" : "=r"(u) : "f"(x));
    return __uint_as_float(u);
}

// ---------------------------------------------------------------------------
// Packed-fragment TF32 GEMM: C[m,n] = sum_k A[m,k]*B[n,k] + bias[n]
// 128x128x32 tiles, 256 threads (8 warps 4x2), warp tile 32x64.
// Smem layout stores tiles in mma-fragment order:
//   A: float4 slot idx = ((mblk*4+kblk)*8+g)*4 + (tig^kblk)   (1024 float4)
//      float4 = {A[r][k], A[r+8][k], A[r][k+4], A[r+8][k+4]}
//   B: float2 slot idx = ((nblk*4+kblk)*8+g)*4 + (tig^kblk)   (2048 float2)
//      float2 = {B[n][k], B[n][k+4]}
// Double-buffered smem + register prefetch of next k-tile LDG.
// ---------------------------------------------------------------------------
#define TILE_A_F 4096   // floats per A tile buffer (128x32)
#define TILE_B_F 4096   // floats per B tile buffer (128x32)  [R7 fix: was 2048]
#define GEMM_SMEM_F (2 * TILE_A_F + 2 * TILE_B_F)   // 16384 floats = 64 KB

__device__ __forceinline__ void gemm_ldg(const float* __restrict__ Ab,
                                         const float* __restrict__ Bb,
                                         int K, int k0, int tid,
                                         float* ra, float* rb) {
#pragma unroll
    for (int i = 0; i < 2; i++) {
        int t = tid + i * 256;
        // A task: rows (mblk*16+g, +8), k quad (kblk*8 + khalf*4)
        int khalf = t & 1, kblk = (t >> 1) & 3, g = (t >> 3) & 7, mblk = t >> 6;
        int r = mblk * 16 + g;
        int k = k0 + kblk * 8 + khalf * 4;
        float4 v0 = *(const float4*)(Ab + (size_t)r * K + k);
        float4 v1 = *(const float4*)(Ab + (size_t)(r + 8) * K + k);
        ra[i * 8 + 0] = v0.x; ra[i * 8 + 1] = v0.y; ra[i * 8 + 2] = v0.z; ra[i * 8 + 3] = v0.w;
        ra[i * 8 + 4] = v1.x; ra[i * 8 + 5] = v1.y; ra[i * 8 + 6] = v1.z; ra[i * 8 + 7] = v1.w;
        // B task: row n, k octet kb2*8
        int kb2 = t & 3, n = t >> 2;
        const float* bp = Bb + (size_t)n * K + k0 + kb2 * 8;
        float4 w0 = *(const float4*)(bp);
        float4 w1 = *(const float4*)(bp + 4);
        rb[i * 8 + 0] = w0.x; rb[i * 8 + 1] = w0.y; rb[i * 8 + 2] = w0.z; rb[i * 8 + 3] = w0.w;
        rb[i * 8 + 4] = w1.x; rb[i * 8 + 5] = w1.y; rb[i * 8 + 6] = w1.z; rb[i * 8 + 7] = w1.w;
    }
}

__device__ __forceinline__ void gemm_sts(float* __restrict__ Apk,
                                         float* __restrict__ Bpk,
                                         int tid, const float* ra, const float* rb) {
#pragma unroll
    for (int i = 0; i < 2; i++) {
        int t = tid + i * 256;
        int khalf = t & 1, kblk = (t >> 1) & 3, g = (t >> 3) & 7, mblk = t >> 6;
        int abase = ((mblk * 4 + kblk) * 8 + g) * 4;
#pragma unroll
        for (int e = 0; e < 4; e++) {
            int idx4 = abase + (e ^ kblk);
            *(float2*)&Apk[idx4 * 4 + 2 * khalf] =
                make_float2(f2tf32(ra[i * 8 + e]), f2tf32(ra[i * 8 + 4 + e]));
        }
        int kb2 = t & 3, n = t >> 2;
        int bbase = (((n >> 3) * 4 + kb2) * 8 + (n & 7)) * 4;
#pragma unroll
        for (int e = 0; e < 4; e++) {
            int idx2 = bbase + (e ^ kb2);
            *(float2*)&Bpk[idx2 * 2] =
                make_float2(f2tf32(rb[i * 8 + e]), f2tf32(rb[i * 8 + 4 + e]));
        }
    }
}

__global__ __launch_bounds__(256, 2)
void gemm_tf32_bias(const float* __restrict__ A, const float* __restrict__ Bm,
                    const float* __restrict__ bias, float* __restrict__ C,
                    int M, int N, int K) {
    extern __shared__ float gsm[];
    float* Apk = gsm;                      // [2][4096]
    float* Bpk = gsm + 2 * TILE_A_F;       // [2][4096]

    const int tid = threadIdx.x;
    const int lane = tid & 31;
    const int warp = tid >> 5;
    const int wm = warp >> 1, wn = warp & 1;
    const int g = lane >> 2, tig = lane & 3;
    const int m0 = blockIdx.y << 7, n0 = blockIdx.x << 7;
    const float* Ab = A + (size_t)m0 * K;
    const float* Bb = Bm + (size_t)n0 * K;

    float acc[2][8][4];
#pragma unroll
    for (int mt = 0; mt < 2; mt++)
#pragma unroll
        for (int nt = 0; nt < 8; nt++)
#pragma unroll
            for (int c = 0; c < 4; c++) acc[mt][nt][c] = 0.0f;

    float ra[16], rb[16];
    gemm_ldg(Ab, Bb, K, 0, tid, ra, rb);
    gemm_sts(Apk, Bpk, tid, ra, rb);
    __syncthreads();

    const int NT = K >> 5;
    for (int it = 0; it < NT; it++) {
        if (it + 1 < NT) gemm_ldg(Ab, Bb, K, (it + 1) << 5, tid, ra, rb);

        const float* Ac = Apk + (it & 1) * TILE_A_F;
        const float* Bc = Bpk + (it & 1) * TILE_B_F;
#pragma unroll
        for (int kk = 0; kk < 4; kk++) {
            unsigned a[2][4];
#pragma unroll
            for (int mt = 0; mt < 2; mt++) {
                int idx4 = (((wm * 2 + mt) * 4 + kk) * 8 + g) * 4 + (tig ^ kk);
                float4 af = *(const float4*)&Ac[idx4 * 4];
                a[mt][0] = __float_as_uint(af.x);
                a[mt][1] = __float_as_uint(af.y);
                a[mt][2] = __float_as_uint(af.z);
                a[mt][3] = __float_as_uint(af.w);
            }
            unsigned bfr[8][2];
#pragma unroll
            for (int nt = 0; nt < 8; nt++) {
                int idx2 = (((wn * 8 + nt) * 4 + kk) * 8 + g) * 4 + (tig ^ kk);
                float2 bf = *(const float2*)&Bc[idx2 * 2];
                bfr[nt][0] = __float_as_uint(bf.x);
                bfr[nt][1] = __float_as_uint(bf.y);
            }
#pragma unroll
            for (int nt = 0; nt < 8; nt++)
#pragma unroll
                for (int mt = 0; mt < 2; mt++) {
                    asm volatile(
                        "mma.sync.aligned.m16n8k8.row.col.f32.tf32.tf32.f32 "
                        "{%0,%1,%2,%3}, {%4,%5,%6,%7}, {%8,%9}, {%0,%1,%2,%3};"
                        : "+f"(acc[mt][nt][0]), "+f"(acc[mt][nt][1]),
                          "+f"(acc[mt][nt][2]), "+f"(acc[mt][nt][3])
                        : "r"(a[mt][0]), "r"(a[mt][1]), "r"(a[mt][2]), "r"(a[mt][3]),
                          "r"(bfr[nt][0]), "r"(bfr[nt][1]));
                }
        }

        if (it + 1 < NT) {
            gemm_sts(Apk + ((it + 1) & 1) * TILE_A_F,
                     Bpk + ((it + 1) & 1) * TILE_B_F, tid, ra, rb);
            __syncthreads();
        }
    }

#pragma unroll
    for (int mt = 0; mt < 2; mt++)
#pragma unroll
        for (int nt = 0; nt < 8; nt++) {
            int col = n0 + wn * 64 + nt * 8 + tig * 2;
            float b0 = bias[col], b1 = bias[col + 1];
            int row0 = m0 + wm * 32 + mt * 16 + g;
            *(float2*)(C + (size_t)row0 * N + col) =
                make_float2(acc[mt][nt][0] + b0, acc[mt][nt][1] + b1);
            *(float2*)(C + (size_t)(row0 + 8) * N + col) =
                make_float2(acc[mt][nt][2] + b0, acc[mt][nt][3] + b1);
        }
}

// ---------------------------------------------------------------------------
// Fused attention (unchanged from R5), M-tile = 64 rows (2 CTAs/SM).
// ---------------------------------------------------------------------------
#define KPAD 36
#define PSTRIDE 228
#define VPAD 68
#define MT 64
#define FUSED_SMEM_FLOATS (MT * PSTRIDE + MT * KPAD + 128 * KPAD)  // 21504 -> 86 KB

__global__ __launch_bounds__(256, 2)
void fused_attn(void) {
    extern __shared__ float sm[];
    float* P  = sm;                      // [64][228]
    float* As = P + MT * PSTRIDE;        // [64][36]
    float* Bs = As + MT * KPAD;          // [128][36]
    float* Vs = As;                      // stage C alias: [32][68]

    const int tid = threadIdx.x;
    const int lane = tid & 31;
    const int warp = tid >> 5;
    const int wm = warp >> 1, wn = warp & 1;
    const int g = lane >> 2, tig = lane & 3;

    const int m0 = blockIdx.x << 6;
    const int bh = blockIdx.y;
    const int b = bh / NHEADS, h = bh - b * NHEADS;
    const float* qkv = g_qkv + (size_t)b * SEQ * QKV3;
    const int hoff = h * HD;
    const float scale = 0.125f;

    const int lr = tid >> 3;
    const int lc = (tid & 7) << 2;

    // ===== Stage A =====
    const float* rb = g_relbias + (size_t)h * SEQ * SPAD;
#pragma unroll
    for (int n0 = 0; n0 < 256; n0 += 128) {
        float acc[8][4];
#pragma unroll
        for (int nt = 0; nt < 8; nt++)
#pragma unroll
            for (int c = 0; c < 4; c++) acc[nt][c] = 0.0f;

#pragma unroll
        for (int k0 = 0; k0 < HD; k0 += 32) {
#pragma unroll
            for (int it = 0; it < 2; it++) {
                int r = lr + it * 32;
                int qi = min(m0 + r, SEQ - 1);
                float4 av = *(const float4*)(qkv + (size_t)qi * QKV3 + hoff + k0 + lc);
                *(float4*)&As[r * KPAD + lc] =
                    make_float4(f2tf32(av.x * scale), f2tf32(av.y * scale),
                                f2tf32(av.z * scale), f2tf32(av.w * scale));
            }
#pragma unroll
            for (int it = 0; it < 4; it++) {
                int r = lr + it * 32;
                int kj = min(n0 + r, SEQ - 1);
                float4 bv = *(const float4*)(qkv + (size_t)kj * QKV3 + CDIM + hoff + k0 + lc);
                *(float4*)&Bs[r * KPAD + lc] =
                    make_float4(f2tf32(bv.x), f2tf32(bv.y), f2tf32(bv.z), f2tf32(bv.w));
            }
            __syncthreads();
#pragma unroll
            for (int kk = 0; kk < 4; kk++) {
                const int kb = kk * 8;
                unsigned a[4];
                {
                    const float* ar0 = &As[(wm * 16 + g) * KPAD + kb];
                    const float* ar1 = &As[(wm * 16 + g + 8) * KPAD + kb];
                    a[0] = __float_as_uint(ar0[tig]);
                    a[1] = __float_as_uint(ar1[tig]);
                    a[2] = __float_as_uint(ar0[tig + 4]);
                    a[3] = __float_as_uint(ar1[tig + 4]);
                }
                unsigned bfr[8][2];
#pragma unroll
                for (int nt = 0; nt < 8; nt++) {
                    const float* br = &Bs[(wn * 64 + nt * 8 + g) * KPAD + kb];
                    bfr[nt][0] = __float_as_uint(br[tig]);
                    bfr[nt][1] = __float_as_uint(br[tig + 4]);
                }
#pragma unroll
                for (int nt = 0; nt < 8; nt++) {
                    asm volatile(
                        "mma.sync.aligned.m16n8k8.row.col.f32.tf32.tf32.f32 "
                        "{%0,%1,%2,%3}, {%4,%5,%6,%7}, {%8,%9}, {%0,%1,%2,%3};"
                        : "+f"(acc[nt][0]), "+f"(acc[nt][1]),
                          "+f"(acc[nt][2]), "+f"(acc[nt][3])
                        : "r"(a[0]), "r"(a[1]), "r"(a[2]), "r"(a[3]),
                          "r"(bfr[nt][0]), "r"(bfr[nt][1]));
                }
            }
            __syncthreads();
        }

#pragma unroll
        for (int nt = 0; nt < 8; nt++) {
            int col = n0 + wn * 64 + nt * 8 + tig * 2;
            if (col >= PSTRIDE) continue;
#pragma unroll
            for (int half = 0; half < 2; half++) {
                int rloc = wm * 16 + g + half * 8;
                int grow = min(m0 + rloc, SEQ - 1);
                float s0 = acc[nt][half * 2 + 0];
                float s1 = acc[nt][half * 2 + 1];
                P[rloc * PSTRIDE + col] =
                    (col < SEQ) ? s0 + rb[(size_t)grow * SPAD + col] : -1e30f;
                P[rloc * PSTRIDE + col + 1] =
                    (col + 1 < SEQ) ? s1 + rb[(size_t)grow * SPAD + col + 1] : -1e30f;
            }
        }
    }
    __syncthreads();

    // ===== Stage B: softmax =====
    for (int rloc = warp; rloc < MT; rloc += 8) {
        float* pr = P + rloc * PSTRIDE;
        float mx = -1e30f;
        float ev[7];
#pragma unroll
        for (int t = 0; t < 7; t++) {
            ev[t] = pr[lane + t * 32];
            mx = fmaxf(mx, ev[t]);
        }
#pragma unroll
        for (int o = 16; o; o >>= 1) mx = fmaxf(mx, __shfl_xor_sync(0xffffffffu, mx, o));
        float sum = 0.f;
#pragma unroll
        for (int t = 0; t < 7; t++) {
            ev[t] = __expf(ev[t] - mx);
            sum += ev[t];
        }
#pragma unroll
        for (int o = 16; o; o >>= 1) sum += __shfl_xor_sync(0xffffffffu, sum, o);
        float inv = 1.0f / sum;
#pragma unroll
        for (int t = 0; t < 7; t++) pr[lane + t * 32] = f2tf32(ev[t] * inv);
    }

    // ===== Stage C: O = P * V =====
    float acc[4][4];
#pragma unroll
    for (int nt = 0; nt < 4; nt++)
#pragma unroll
        for (int c = 0; c < 4; c++) acc[nt][c] = 0.0f;

    const int vr = tid >> 4;
    const int vc = (tid & 15) << 2;

    for (int k0 = 0; k0 < SPAD; k0 += 32) {
        __syncthreads();
#pragma unroll
        for (int it = 0; it < 2; it++) {
            int j = vr + it * 16;
            int vj = min(k0 + j, SEQ - 1);
            float4 vv = *(const float4*)(qkv + (size_t)vj * QKV3 + 2 * CDIM + hoff + vc);
            *(float4*)&Vs[j * VPAD + vc] =
                make_float4(f2tf32(vv.x), f2tf32(vv.y), f2tf32(vv.z), f2tf32(vv.w));
        }
        __syncthreads();
#pragma unroll
        for (int kk = 0; kk < 4; kk++) {
            const int kb = kk * 8;
            unsigned a[4];
            {
                const float* ar0 = &P[(wm * 16 + g) * PSTRIDE + k0 + kb];
                const float* ar1 = &P[(wm * 16 + g + 8) * PSTRIDE + k0 + kb];
                a[0] = __float_as_uint(ar0[tig]);
                a[1] = __float_as_uint(ar1[tig]);
                a[2] = __float_as_uint(ar0[tig + 4]);
                a[3] = __float_as_uint(ar1[tig + 4]);
            }
            unsigned bfr[4][2];
#pragma unroll
            for (int nt = 0; nt < 4; nt++) {
                int n = wn * 32 + nt * 8 + g;
                bfr[nt][0] = __float_as_uint(Vs[(kb + tig) * VPAD + n]);
                bfr[nt][1] = __float_as_uint(Vs[(kb + tig + 4) * VPAD + n]);
            }
#pragma unroll
            for (int nt = 0; nt < 4; nt++) {
                asm volatile(
                    "mma.sync.aligned.m16n8k8.row.col.f32.tf32.tf32.f32 "
                    "{%0,%1,%2,%3}, {%4,%5,%6,%7}, {%8,%9}, {%0,%1,%2,%3};"
                    : "+f"(acc[nt][0]), "+f"(acc[nt][1]),
                      "+f"(acc[nt][2]), "+f"(acc[nt][3])
                    : "r"(a[0]), "r"(a[1]), "r"(a[2]), "r"(a[3]),
                      "r"(bfr[nt][0]), "r"(bfr[nt][1]));
            }
        }
    }

#pragma unroll
    for (int nt = 0; nt < 4; nt++) {
        int col = wn * 32 + nt * 8 + tig * 2;
        int row0 = m0 + wm * 16 + g;
        if (row0 < SEQ)
            *(float2*)(g_attn + ((size_t)b * SEQ + row0) * CDIM + hoff + col) =
                make_float2(acc[nt][0], acc[nt][1]);
        int row1 = row0 + 8;
        if (row1 < SEQ)
            *(float2*)(g_attn + ((size_t)b * SEQ + row1) * CDIM + hoff + col) =
                make_float2(acc[nt][2], acc[nt][3]);
    }
}

// ---------------------------------------------------------------------------
extern "C" void kernel_launch(void* const* d_in, const int* in_sizes, int n_in,
                              void* d_out, int out_size) {
    const float* x      = (const float*)d_in[0];
    const float* qkv_w  = (const float*)d_in[1];
    const float* q_bias = (const float*)d_in[2];
    const float* v_bias = (const float*)d_in[3];
    const float* table  = (const float*)d_in[4];
    const float* proj_w = (const float*)d_in[5];
    const float* proj_b = (const float*)d_in[6];
    const int*   relidx = (const int*)d_in[7];
    float* out = (float*)d_out;

    float *qkv_p, *attn_p, *bias_p;
    cudaGetSymbolAddress((void**)&qkv_p, g_qkv);
    cudaGetSymbolAddress((void**)&attn_p, g_attn);
    cudaGetSymbolAddress((void**)&bias_p, g_bias);

    const size_t gemm_smem = (size_t)GEMM_SMEM_F * sizeof(float);        // 64 KB
    const size_t fused_smem = (size_t)FUSED_SMEM_FLOATS * sizeof(float); // 86 KB
    cudaFuncSetAttribute(gemm_tf32_bias, cudaFuncAttributeMaxDynamicSharedMemorySize,
                         (int)gemm_smem);
    cudaFuncSetAttribute(fused_attn, cudaFuncAttributeMaxDynamicSharedMemorySize,
                         (int)fused_smem);

    build_bias_kernel<<<(QKV3 + 255) / 256, 256>>>(q_bias, v_bias);
    build_relbias_kernel<<<(NHEADS * SEQ * SPAD + 255) / 256, 256>>>(table, relidx);

    // qkv = x @ qkv_w^T + bias
    gemm_tf32_bias<<<dim3(QKV3 / 128, MROWS / 128), 256, gemm_smem>>>(
        x, qkv_w, bias_p, qkv_p, MROWS, QKV3, CDIM);

    // fused attention -> g_attn
    fused_attn<<<dim3(4, BH), 256, fused_smem>>>();

    // out = attn @ proj_w^T + proj_b
    gemm_tf32_bias<<<dim3(CDIM / 128, MROWS / 128), 256, gemm_smem>>>(
        attn_p, proj_w, proj_b, out, MROWS, CDIM, CDIM);
}

// round 10
// speedup vs baseline: 5.7688x; 1.0452x over previous
#include <cuda_runtime.h>

#define NHEADS 12
#define SEQ 197
#define CDIM 768
#define HD 64
#define QKV3 2304
#define BATCH 128
#define MROWS (BATCH * SEQ)   // 25216
#define SPAD 224              // padded col count for relbias
#define BH (BATCH * NHEADS)   // 1536

// Scratch (device globals: allocation-guard safe)
__device__ float g_qkv[(size_t)BATCH * SEQ * QKV3];        // 232 MB
__device__ float g_attn[(size_t)BATCH * SEQ * CDIM];       // 77 MB
__device__ float g_relbias[(size_t)NHEADS * SEQ * SPAD];   // 2.1 MB
__device__ float g_bias[QKV3];

// ---------------------------------------------------------------------------
__global__ void build_bias_kernel(const float* __restrict__ qb,
                                  const float* __restrict__ vb) {
    int i = blockIdx.x * blockDim.x + threadIdx.x;
    if (i < QKV3) {
        g_bias[i] = (i < CDIM) ? qb[i] : ((i < 2 * CDIM) ? 0.0f : vb[i - 2 * CDIM]);
    }
}

__global__ void build_relbias_kernel(const float* __restrict__ table,
                                     const int* __restrict__ relidx) {
    int idx = blockIdx.x * blockDim.x + threadIdx.x;
    if (idx >= NHEADS * SEQ * SPAD) return;
    int h = idx / (SEQ * SPAD);
    int rem = idx - h * SEQ * SPAD;
    int i = rem / SPAD;
    int j = rem - i * SPAD;
    g_relbias[idx] = (j < SEQ) ? table[relidx[i * SEQ + j] * NHEADS + h] : 0.0f;
}

__device__ __forceinline__ float f2tf32(float x) {
    unsigned u;
    asm("cvt.rna.tf32.f32 %0, %1;" : "=r"(u) : "f"(x));
    return __uint_as_float(u);
}

// ---------------------------------------------------------------------------
// Packed-fragment TF32 GEMM (unchanged from R8).
// ---------------------------------------------------------------------------
#define TILE_A_F 4096
#define TILE_B_F 4096
#define GEMM_SMEM_F (2 * TILE_A_F + 2 * TILE_B_F)   // 64 KB

__device__ __forceinline__ void gemm_ldg(const float* __restrict__ Ab,
                                         const float* __restrict__ Bb,
                                         int K, int k0, int tid,
                                         float* ra, float* rb) {
#pragma unroll
    for (int i = 0; i < 2; i++) {
        int t = tid + i * 256;
        int khalf = t & 1, kblk = (t >> 1) & 3, g = (t >> 3) & 7, mblk = t >> 6;
        int r = mblk * 16 + g;
        int k = k0 + kblk * 8 + khalf * 4;
        float4 v0 = *(const float4*)(Ab + (size_t)r * K + k);
        float4 v1 = *(const float4*)(Ab + (size_t)(r + 8) * K + k);
        ra[i * 8 + 0] = v0.x; ra[i * 8 + 1] = v0.y; ra[i * 8 + 2] = v0.z; ra[i * 8 + 3] = v0.w;
        ra[i * 8 + 4] = v1.x; ra[i * 8 + 5] = v1.y; ra[i * 8 + 6] = v1.z; ra[i * 8 + 7] = v1.w;
        int kb2 = t & 3, n = t >> 2;
        const float* bp = Bb + (size_t)n * K + k0 + kb2 * 8;
        float4 w0 = *(const float4*)(bp);
        float4 w1 = *(const float4*)(bp + 4);
        rb[i * 8 + 0] = w0.x; rb[i * 8 + 1] = w0.y; rb[i * 8 + 2] = w0.z; rb[i * 8 + 3] = w0.w;
        rb[i * 8 + 4] = w1.x; rb[i * 8 + 5] = w1.y; rb[i * 8 + 6] = w1.z; rb[i * 8 + 7] = w1.w;
    }
}

__device__ __forceinline__ void gemm_sts(float* __restrict__ Apk,
                                         float* __restrict__ Bpk,
                                         int tid, const float* ra, const float* rb) {
#pragma unroll
    for (int i = 0; i < 2; i++) {
        int t = tid + i * 256;
        int khalf = t & 1, kblk = (t >> 1) & 3, g = (t >> 3) & 7, mblk = t >> 6;
        int abase = ((mblk * 4 + kblk) * 8 + g) * 4;
#pragma unroll
        for (int e = 0; e < 4; e++) {
            int idx4 = abase + (e ^ kblk);
            *(float2*)&Apk[idx4 * 4 + 2 * khalf] =
                make_float2(f2tf32(ra[i * 8 + e]), f2tf32(ra[i * 8 + 4 + e]));
        }
        int kb2 = t & 3, n = t >> 2;
        int bbase = (((n >> 3) * 4 + kb2) * 8 + (n & 7)) * 4;
#pragma unroll
        for (int e = 0; e < 4; e++) {
            int idx2 = bbase + (e ^ kb2);
            *(float2*)&Bpk[idx2 * 2] =
                make_float2(f2tf32(rb[i * 8 + e]), f2tf32(rb[i * 8 + 4 + e]));
        }
    }
}

__global__ __launch_bounds__(256, 2)
void gemm_tf32_bias(const float* __restrict__ A, const float* __restrict__ Bm,
                    const float* __restrict__ bias, float* __restrict__ C,
                    int M, int N, int K) {
    extern __shared__ float gsm[];
    float* Apk = gsm;
    float* Bpk = gsm + 2 * TILE_A_F;

    const int tid = threadIdx.x;
    const int lane = tid & 31;
    const int warp = tid >> 5;
    const int wm = warp >> 1, wn = warp & 1;
    const int g = lane >> 2, tig = lane & 3;
    const int m0 = blockIdx.y << 7, n0 = blockIdx.x << 7;
    const float* Ab = A + (size_t)m0 * K;
    const float* Bb = Bm + (size_t)n0 * K;

    float acc[2][8][4];
#pragma unroll
    for (int mt = 0; mt < 2; mt++)
#pragma unroll
        for (int nt = 0; nt < 8; nt++)
#pragma unroll
            for (int c = 0; c < 4; c++) acc[mt][nt][c] = 0.0f;

    float ra[16], rb[16];
    gemm_ldg(Ab, Bb, K, 0, tid, ra, rb);
    gemm_sts(Apk, Bpk, tid, ra, rb);
    __syncthreads();

    const int NT = K >> 5;
    for (int it = 0; it < NT; it++) {
        if (it + 1 < NT) gemm_ldg(Ab, Bb, K, (it + 1) << 5, tid, ra, rb);

        const float* Ac = Apk + (it & 1) * TILE_A_F;
        const float* Bc = Bpk + (it & 1) * TILE_B_F;
#pragma unroll
        for (int kk = 0; kk < 4; kk++) {
            unsigned a[2][4];
#pragma unroll
            for (int mt = 0; mt < 2; mt++) {
                int idx4 = (((wm * 2 + mt) * 4 + kk) * 8 + g) * 4 + (tig ^ kk);
                float4 af = *(const float4*)&Ac[idx4 * 4];
                a[mt][0] = __float_as_uint(af.x);
                a[mt][1] = __float_as_uint(af.y);
                a[mt][2] = __float_as_uint(af.z);
                a[mt][3] = __float_as_uint(af.w);
            }
            unsigned bfr[8][2];
#pragma unroll
            for (int nt = 0; nt < 8; nt++) {
                int idx2 = (((wn * 8 + nt) * 4 + kk) * 8 + g) * 4 + (tig ^ kk);
                float2 bf = *(const float2*)&Bc[idx2 * 2];
                bfr[nt][0] = __float_as_uint(bf.x);
                bfr[nt][1] = __float_as_uint(bf.y);
            }
#pragma unroll
            for (int nt = 0; nt < 8; nt++)
#pragma unroll
                for (int mt = 0; mt < 2; mt++) {
                    asm volatile(
                        "mma.sync.aligned.m16n8k8.row.col.f32.tf32.tf32.f32 "
                        "{%0,%1,%2,%3}, {%4,%5,%6,%7}, {%8,%9}, {%0,%1,%2,%3};"
                        : "+f"(acc[mt][nt][0]), "+f"(acc[mt][nt][1]),
                          "+f"(acc[mt][nt][2]), "+f"(acc[mt][nt][3])
                        : "r"(a[mt][0]), "r"(a[mt][1]), "r"(a[mt][2]), "r"(a[mt][3]),
                          "r"(bfr[nt][0]), "r"(bfr[nt][1]));
                }
        }

        if (it + 1 < NT) {
            gemm_sts(Apk + ((it + 1) & 1) * TILE_A_F,
                     Bpk + ((it + 1) & 1) * TILE_B_F, tid, ra, rb);
            __syncthreads();
        }
    }

#pragma unroll
    for (int mt = 0; mt < 2; mt++)
#pragma unroll
        for (int nt = 0; nt < 8; nt++) {
            int col = n0 + wn * 64 + nt * 8 + tig * 2;
            float b0 = bias[col], b1 = bias[col + 1];
            int row0 = m0 + wm * 32 + mt * 16 + g;
            *(float2*)(C + (size_t)row0 * N + col) =
                make_float2(acc[mt][nt][0] + b0, acc[mt][nt][1] + b1);
            *(float2*)(C + (size_t)(row0 + 8) * N + col) =
                make_float2(acc[mt][nt][2] + b0, acc[mt][nt][3] + b1);
        }
}

// ---------------------------------------------------------------------------
// Fused attention v2: full-K smem tiles (one sync pair per K-half) +
// register-prefetched V chunks. M-tile 64, 2 CTAs/SM.
// Smem: P[64][228] + Q[64][68] + K[128][68] = 27648 floats = 108 KB.
// ---------------------------------------------------------------------------
#define QSTR 68
#define PSTRIDE 228
#define MT 64
#define P_F (MT * PSTRIDE)          // 14592
#define Q_F (MT * QSTR)             // 4352
#define K_F (128 * QSTR)            // 8704
#define FUSED_SMEM_FLOATS (P_F + Q_F + K_F)   // 27648 -> 108 KB

__global__ __launch_bounds__(256, 2)
void fused_attn(void) {
    extern __shared__ float sm[];
    float* P  = sm;             // [64][228]
    float* Qs = P + P_F;        // [64][68]
    float* Ks = Qs + Q_F;       // [128][68]
    float* Vs = Qs;             // stage C alias: [32][68]

    const int tid = threadIdx.x;
    const int lane = tid & 31;
    const int warp = tid >> 5;
    const int wm = warp >> 1, wn = warp & 1;   // wm 0..3, wn 0..1
    const int g = lane >> 2, tig = lane & 3;

    const int m0 = blockIdx.x << 6;            // 0,64,128,192
    const int bh = blockIdx.y;
    const int b = bh / NHEADS, h = bh - b * NHEADS;
    const float* qkv = g_qkv + (size_t)b * SEQ * QKV3;
    const int hoff = h * HD;
    const float scale = 0.125f;

    // ===== fill Q [64 x 64] (scaled, tf32) =====
#pragma unroll
    for (int it = 0; it < 4; it++) {
        int idx = tid + it * 256;              // 0..1023
        int row = idx >> 4, c4 = (idx & 15) << 2;
        int qi = min(m0 + row, SEQ - 1);
        float4 av = *(const float4*)(qkv + (size_t)qi * QKV3 + hoff + c4);
        *(float4*)&Qs[row * QSTR + c4] =
            make_float4(f2tf32(av.x * scale), f2tf32(av.y * scale),
                        f2tf32(av.z * scale), f2tf32(av.w * scale));
    }

    // ===== Stage A: S = Q*K^T + rel_bias -> P =====
    const float* rbp = g_relbias + (size_t)h * SEQ * SPAD;
#pragma unroll
    for (int n0 = 0; n0 < 256; n0 += 128) {
        // fill K-half [128 x 64]
#pragma unroll
        for (int it = 0; it < 8; it++) {
            int idx = tid + it * 256;          // 0..2047
            int row = idx >> 4, c4 = (idx & 15) << 2;
            int kj = min(n0 + row, SEQ - 1);
            float4 bv = *(const float4*)(qkv + (size_t)kj * QKV3 + CDIM + hoff + c4);
            *(float4*)&Ks[row * QSTR + c4] =
                make_float4(f2tf32(bv.x), f2tf32(bv.y), f2tf32(bv.z), f2tf32(bv.w));
        }
        __syncthreads();

        float acc[8][4];
#pragma unroll
        for (int nt = 0; nt < 8; nt++)
#pragma unroll
            for (int c = 0; c < 4; c++) acc[nt][c] = 0.0f;

#pragma unroll
        for (int kk = 0; kk < 8; kk++) {
            const int kb = kk * 8;
            unsigned a[4];
            {
                const float* ar0 = &Qs[(wm * 16 + g) * QSTR + kb];
                const float* ar1 = &Qs[(wm * 16 + g + 8) * QSTR + kb];
                a[0] = __float_as_uint(ar0[tig]);
                a[1] = __float_as_uint(ar1[tig]);
                a[2] = __float_as_uint(ar0[tig + 4]);
                a[3] = __float_as_uint(ar1[tig + 4]);
            }
            unsigned bfr[8][2];
#pragma unroll
            for (int nt = 0; nt < 8; nt++) {
                const float* br = &Ks[(wn * 64 + nt * 8 + g) * QSTR + kb];
                bfr[nt][0] = __float_as_uint(br[tig]);
                bfr[nt][1] = __float_as_uint(br[tig + 4]);
            }
#pragma unroll
            for (int nt = 0; nt < 8; nt++) {
                asm volatile(
                    "mma.sync.aligned.m16n8k8.row.col.f32.tf32.tf32.f32 "
                    "{%0,%1,%2,%3}, {%4,%5,%6,%7}, {%8,%9}, {%0,%1,%2,%3};"
                    : "+f"(acc[nt][0]), "+f"(acc[nt][1]),
                      "+f"(acc[nt][2]), "+f"(acc[nt][3])
                    : "r"(a[0]), "r"(a[1]), "r"(a[2]), "r"(a[3]),
                      "r"(bfr[nt][0]), "r"(bfr[nt][1]));
            }
        }

        // epilogue -> smem P (pads -1e30); rel_bias as float2
#pragma unroll
        for (int nt = 0; nt < 8; nt++) {
            int col = n0 + wn * 64 + nt * 8 + tig * 2;
            if (col >= SPAD) continue;
#pragma unroll
            for (int half = 0; half < 2; half++) {
                int rloc = wm * 16 + g + half * 8;
                int grow = min(m0 + rloc, SEQ - 1);
                float2 rv2 = *(const float2*)(rbp + (size_t)grow * SPAD + col);
                float p0 = (col < SEQ) ? acc[nt][half * 2 + 0] + rv2.x : -1e30f;
                float p1 = (col + 1 < SEQ) ? acc[nt][half * 2 + 1] + rv2.y : -1e30f;
                *(float2*)&P[rloc * PSTRIDE + col] = make_float2(p0, p1);
            }
        }
        __syncthreads();
    }

    // ===== prefetch V chunk 0 (hidden behind softmax) =====
    const int vr = tid >> 4;            // 0..15
    const int vc = (tid & 15) << 2;     // 0..60
    float rv[8];
#pragma unroll
    for (int it = 0; it < 2; it++) {
        int j = vr + it * 16;
        int vj = min(j, SEQ - 1);
        float4 vv = *(const float4*)(qkv + (size_t)vj * QKV3 + 2 * CDIM + hoff + vc);
        rv[it * 4 + 0] = vv.x; rv[it * 4 + 1] = vv.y;
        rv[it * 4 + 2] = vv.z; rv[it * 4 + 3] = vv.w;
    }

    // ===== Stage B: softmax (warp per row, 8 rows per warp) =====
    for (int rloc = warp; rloc < MT; rloc += 8) {
        float* pr = P + rloc * PSTRIDE;
        float mx = -1e30f;
        float ev[7];
#pragma unroll
        for (int t = 0; t < 7; t++) {
            ev[t] = pr[lane + t * 32];
            mx = fmaxf(mx, ev[t]);
        }
#pragma unroll
        for (int o = 16; o; o >>= 1) mx = fmaxf(mx, __shfl_xor_sync(0xffffffffu, mx, o));
        float sum = 0.f;
#pragma unroll
        for (int t = 0; t < 7; t++) {
            ev[t] = __expf(ev[t] - mx);
            sum += ev[t];
        }
#pragma unroll
        for (int o = 16; o; o >>= 1) sum += __shfl_xor_sync(0xffffffffu, sum, o);
        float inv = 1.0f / sum;
#pragma unroll
        for (int t = 0; t < 7; t++) pr[lane + t * 32] = f2tf32(ev[t] * inv);
    }
    __syncthreads();   // softmax done; Qs region now reusable as Vs

    // ===== Stage C: O = P * V with register-prefetched V chunks =====
    float acc[4][4];
#pragma unroll
    for (int nt = 0; nt < 4; nt++)
#pragma unroll
        for (int c = 0; c < 4; c++) acc[nt][c] = 0.0f;

    for (int k0 = 0; k0 < SPAD; k0 += 32) {
        // store current chunk
#pragma unroll
        for (int it = 0; it < 2; it++) {
            int j = vr + it * 16;
            *(float4*)&Vs[j * QSTR + vc] =
                make_float4(f2tf32(rv[it * 4 + 0]), f2tf32(rv[it * 4 + 1]),
                            f2tf32(rv[it * 4 + 2]), f2tf32(rv[it * 4 + 3]));
        }
        __syncthreads();
        // prefetch next chunk
        if (k0 + 32 < SPAD) {
#pragma unroll
            for (int it = 0; it < 2; it++) {
                int j = vr + it * 16;
                int vj = min(k0 + 32 + j, SEQ - 1);
                float4 vv = *(const float4*)(qkv + (size_t)vj * QKV3 + 2 * CDIM + hoff + vc);
                rv[it * 4 + 0] = vv.x; rv[it * 4 + 1] = vv.y;
                rv[it * 4 + 2] = vv.z; rv[it * 4 + 3] = vv.w;
            }
        }
#pragma unroll
        for (int kk = 0; kk < 4; kk++) {
            const int kb = kk * 8;
            unsigned a[4];
            {
                const float* ar0 = &P[(wm * 16 + g) * PSTRIDE + k0 + kb];
                const float* ar1 = &P[(wm * 16 + g + 8) * PSTRIDE + k0 + kb];
                a[0] = __float_as_uint(ar0[tig]);
                a[1] = __float_as_uint(ar1[tig]);
                a[2] = __float_as_uint(ar0[tig + 4]);
                a[3] = __float_as_uint(ar1[tig + 4]);
            }
            unsigned bfr[4][2];
#pragma unroll
            for (int nt = 0; nt < 4; nt++) {
                int n = wn * 32 + nt * 8 + g;
                bfr[nt][0] = __float_as_uint(Vs[(kb + tig) * QSTR + n]);
                bfr[nt][1] = __float_as_uint(Vs[(kb + tig + 4) * QSTR + n]);
            }
#pragma unroll
            for (int nt = 0; nt < 4; nt++) {
                asm volatile(
                    "mma.sync.aligned.m16n8k8.row.col.f32.tf32.tf32.f32 "
                    "{%0,%1,%2,%3}, {%4,%5,%6,%7}, {%8,%9}, {%0,%1,%2,%3};"
                    : "+f"(acc[nt][0]), "+f"(acc[nt][1]),
                      "+f"(acc[nt][2]), "+f"(acc[nt][3])
                    : "r"(a[0]), "r"(a[1]), "r"(a[2]), "r"(a[3]),
                      "r"(bfr[nt][0]), "r"(bfr[nt][1]));
            }
        }
        __syncthreads();
    }

#pragma unroll
    for (int nt = 0; nt < 4; nt++) {
        int col = wn * 32 + nt * 8 + tig * 2;
        int row0 = m0 + wm * 16 + g;
        if (row0 < SEQ)
            *(float2*)(g_attn + ((size_t)b * SEQ + row0) * CDIM + hoff + col) =
                make_float2(acc[nt][0], acc[nt][1]);
        int row1 = row0 + 8;
        if (row1 < SEQ)
            *(float2*)(g_attn + ((size_t)b * SEQ + row1) * CDIM + hoff + col) =
                make_float2(acc[nt][2], acc[nt][3]);
    }
}

// ---------------------------------------------------------------------------
extern "C" void kernel_launch(void* const* d_in, const int* in_sizes, int n_in,
                              void* d_out, int out_size) {
    const float* x      = (const float*)d_in[0];
    const float* qkv_w  = (const float*)d_in[1];
    const float* q_bias = (const float*)d_in[2];
    const float* v_bias = (const float*)d_in[3];
    const float* table  = (const float*)d_in[4];
    const float* proj_w = (const float*)d_in[5];
    const float* proj_b = (const float*)d_in[6];
    const int*   relidx = (const int*)d_in[7];
    float* out = (float*)d_out;

    float *qkv_p, *attn_p, *bias_p;
    cudaGetSymbolAddress((void**)&qkv_p, g_qkv);
    cudaGetSymbolAddress((void**)&attn_p, g_attn);
    cudaGetSymbolAddress((void**)&bias_p, g_bias);

    const size_t gemm_smem = (size_t)GEMM_SMEM_F * sizeof(float);        // 64 KB
    const size_t fused_smem = (size_t)FUSED_SMEM_FLOATS * sizeof(float); // 108 KB
    cudaFuncSetAttribute(gemm_tf32_bias, cudaFuncAttributeMaxDynamicSharedMemorySize,
                         (int)gemm_smem);
    cudaFuncSetAttribute(fused_attn, cudaFuncAttributeMaxDynamicSharedMemorySize,
                         (int)fused_smem);

    build_bias_kernel<<<(QKV3 + 255) / 256, 256>>>(q_bias, v_bias);
    build_relbias_kernel<<<(NHEADS * SEQ * SPAD + 255) / 256, 256>>>(table, relidx);

    // qkv = x @ qkv_w^T + bias
    gemm_tf32_bias<<<dim3(QKV3 / 128, MROWS / 128), 256, gemm_smem>>>(
        x, qkv_w, bias_p, qkv_p, MROWS, QKV3, CDIM);

    // fused attention -> g_attn
    fused_attn<<<dim3(4, BH), 256, fused_smem>>>();

    // out = attn @ proj_w^T + proj_b
    gemm_tf32_bias<<<dim3(CDIM / 128, MROWS / 128), 256, gemm_smem>>>(
        attn_p, proj_w, proj_b, out, MROWS, CDIM, CDIM);
}